// round 14
// baseline (speedup 1.0000x reference)
#include <cuda_runtime.h>
#include <cuda_bf16.h>
#include <cstdint>

#define T_TOK 4096
#define DM    1024
#define DFF   4096
#define KSEL  256
#define DH    64
#define DH2   32
#define DR    128
#define TILEB 16384
#define MARG  4e-4f

typedef unsigned long long ull;

__device__ float g_xn[(size_t)T_TOK * DM];
__device__ float g_h[(size_t)T_TOK * DM];
__device__ float g_scores[(size_t)T_TOK * DFF];
__device__ float g_z[(size_t)T_TOK * DFF];
__device__ float g_asel[(size_t)T_TOK * KSEL];
__device__ int   g_idx[(size_t)T_TOK * KSEL];

__device__ ull g_xt0[(size_t)T_TOK * DM / 4],  g_xt1[(size_t)T_TOK * DM / 4];
__device__ ull g_w1t0[(size_t)DFF * DM / 4],   g_w1t1[(size_t)DFF * DM / 4];
__device__ ull g_ht0[(size_t)T_TOK * DM / 4],  g_ht1[(size_t)T_TOK * DM / 4];
__device__ ull g_wr2t0[(size_t)DFF * DM / 4],  g_wr2t1[(size_t)DFF * DM / 4];
__device__ ull g_at0[(size_t)T_TOK * DFF / 4], g_at1[(size_t)T_TOK * DFF / 4];   // zero-init at load
__device__ ull g_w2t0[(size_t)DM * DFF / 4],   g_w2t1[(size_t)DM * DFF / 4];
__device__ ull g_ct0[(size_t)T_TOK * KSEL * DH / 4], g_ct1[(size_t)T_TOK * KSEL * DH / 4];
__device__ ull g_rt0[TILEB / 8], g_rt1[TILEB / 8];

__device__ __forceinline__ float gelu_f(float x) {
    return 0.5f * x * (1.0f + erff(x * 0.7071067811865475f));
}
__device__ __forceinline__ ull pack2(float lo, float hi) {
    ull r; asm("mov.b64 %0, {%1,%2};" : "=l"(r) : "f"(lo), "f"(hi)); return r;
}
__device__ __forceinline__ void unpack2(ull v, float &lo, float &hi) {
    asm("mov.b64 {%0,%1}, %2;" : "=f"(lo), "=f"(hi) : "l"(v));
}
__device__ __forceinline__ ull ffma2(ull a, ull b, ull c) {
    ull d; asm("fma.rn.f32x2 %0, %1, %2, %3;" : "=l"(d) : "l"(a), "l"(b), "l"(c));
    return d;
}
__device__ __forceinline__ uint32_t s2u(const void* p) {
    uint32_t a;
    asm("{ .reg .u64 t; cvta.to.shared.u64 t, %1; cvt.u32.u64 %0, t; }" : "=r"(a) : "l"(p));
    return a;
}
__device__ __forceinline__ void cp16(uint32_t d, const void* s) {
    asm volatile("cp.async.cg.shared.global [%0], [%1], 16;" :: "r"(d), "l"(s) : "memory");
}
__device__ __forceinline__ void cp_commit() {
    asm volatile("cp.async.commit_group;" ::: "memory");
}
template <int N>
__device__ __forceinline__ void cp_wait() {
    asm volatile("cp.async.wait_group %0;" :: "n"(N) : "memory");
}
__device__ __forceinline__ void ldsm4(uint32_t* r, uint32_t addr) {
    asm volatile("ldmatrix.sync.aligned.m8n8.x4.shared.b16 {%0,%1,%2,%3}, [%4];"
                 : "=r"(r[0]), "=r"(r[1]), "=r"(r[2]), "=r"(r[3]) : "r"(addr));
}
__device__ __forceinline__ void mma16816(float* d, const uint32_t* a, const uint32_t* b) {
    asm volatile(
        "mma.sync.aligned.m16n8k16.row.col.f32.bf16.bf16.f32 "
        "{%0,%1,%2,%3}, {%4,%5,%6,%7}, {%8,%9}, {%0,%1,%2,%3};"
        : "+f"(d[0]), "+f"(d[1]), "+f"(d[2]), "+f"(d[3])
        : "r"(a[0]), "r"(a[1]), "r"(a[2]), "r"(a[3]), "r"(b[0]), "r"(b[1]));
}

// ---------------- layernorm -------------------------------------------------
__global__ void __launch_bounds__(256) k_ln(const float* __restrict__ x,
                                            const float* __restrict__ w,
                                            const float* __restrict__ b) {
    __shared__ float red[8];
    int t = blockIdx.x, tid = threadIdx.x;
    float4 v = ((const float4*)(x + (size_t)t * DM))[tid];
    float s = v.x + v.y + v.z + v.w;
    #pragma unroll
    for (int o = 16; o; o >>= 1) s += __shfl_down_sync(0xffffffffu, s, o);
    if ((tid & 31) == 0) red[tid >> 5] = s;
    __syncthreads();
    float tot = 0.f;
    #pragma unroll
    for (int i = 0; i < 8; i++) tot += red[i];
    float mu = tot * (1.0f / DM);
    __syncthreads();
    float dx = v.x - mu, dy = v.y - mu, dz = v.z - mu, dw = v.w - mu;
    float q = dx * dx + dy * dy + dz * dz + dw * dw;
    #pragma unroll
    for (int o = 16; o; o >>= 1) q += __shfl_down_sync(0xffffffffu, q, o);
    if ((tid & 31) == 0) red[tid >> 5] = q;
    __syncthreads();
    float vt = 0.f;
    #pragma unroll
    for (int i = 0; i < 8; i++) vt += red[i];
    float inv = rsqrtf(vt * (1.0f / DM) + 1e-5f);
    float4 wv = ((const float4*)w)[tid];
    float4 bv = ((const float4*)b)[tid];
    float4 o;
    o.x = dx * inv * wv.x + bv.x;
    o.y = dy * inv * wv.y + bv.y;
    o.z = dz * inv * wv.z + bv.z;
    o.w = dw * inv * wv.w + bv.w;
    ((float4*)(g_xn + (size_t)t * DM))[tid] = o;
}

// ---------------- fp32 FFMA2 GEMM, B-skewed (bit-exact vs R1) ---------------
__device__ __forceinline__ void gemm_core(const float* __restrict__ A,
                                          const float* __restrict__ B,
                                          float* __restrict__ C,
                                          int N, bool do_gelu) {
    const int K = 1024;
    __shared__ float As[8][128];
    __shared__ float Bs[8][160];
    int tid = threadIdx.x;
    int m0 = blockIdx.y * 128, n0 = blockIdx.x * 128;
    int lr = tid >> 1;
    int lc = (tid & 1) * 4;
    const float* Ag = A + (size_t)(m0 + lr) * K + lc;
    const float* Bg = B + (size_t)(n0 + lr) * K + lc;
    int tx = tid & 15, ty = tid >> 4;
    int mo = ty * 8, no = tx * 8;
    int lrs = lr + ((lr >> 3) << 1);
    int nos = no + ((no >> 3) << 1);

    ull acc[32];
    #pragma unroll
    for (int i = 0; i < 32; i++) acc[i] = 0ull;

    float4 a4 = *(const float4*)Ag;
    float4 b4 = *(const float4*)Bg;

    #pragma unroll 1
    for (int kt = 0; kt < K / 8; kt++) {
        As[lc + 0][lr] = a4.x; As[lc + 1][lr] = a4.y;
        As[lc + 2][lr] = a4.z; As[lc + 3][lr] = a4.w;
        Bs[lc + 0][lrs] = b4.x; Bs[lc + 1][lrs] = b4.y;
        Bs[lc + 2][lrs] = b4.z; Bs[lc + 3][lrs] = b4.w;
        __syncthreads();
        if (kt + 1 < K / 8) {
            a4 = *(const float4*)(Ag + (kt + 1) * 8);
            b4 = *(const float4*)(Bg + (kt + 1) * 8);
        }
        #pragma unroll
        for (int k = 0; k < 8; k++) {
            float4 aA = *(const float4*)&As[k][mo];
            float4 aB = *(const float4*)&As[k][mo + 4];
            const ull* bp = (const ull*)&Bs[k][nos];
            ull b0 = bp[0], b1 = bp[1], b2 = bp[2], b3 = bp[3];
            float am[8] = {aA.x, aA.y, aA.z, aA.w, aB.x, aB.y, aB.z, aB.w};
            #pragma unroll
            for (int i = 0; i < 8; i++) {
                ull ap = pack2(am[i], am[i]);
                acc[i * 4 + 0] = ffma2(ap, b0, acc[i * 4 + 0]);
                acc[i * 4 + 1] = ffma2(ap, b1, acc[i * 4 + 1]);
                acc[i * 4 + 2] = ffma2(ap, b2, acc[i * 4 + 2]);
                acc[i * 4 + 3] = ffma2(ap, b3, acc[i * 4 + 3]);
            }
        }
        __syncthreads();
    }
    #pragma unroll
    for (int i = 0; i < 8; i++) {
        float* crow = C + (size_t)(m0 + mo + i) * N + n0 + no;
        #pragma unroll
        for (int p = 0; p < 4; p++) {
            float lo, hi;
            unpack2(acc[i * 4 + p], lo, hi);
            if (do_gelu) { lo = gelu_f(lo); hi = gelu_f(hi); }
            crow[2 * p]     = lo;
            crow[2 * p + 1] = hi;
        }
    }
}

__global__ void __launch_bounds__(256, 2) k_gemm_router1(const float* __restrict__ Wr1) {
    gemm_core(g_xn, Wr1, g_h, DM, true);
}

// ---------------- fp32 -> 2 bf16 term tiles ---------------------------------
template <int WIDTH>
__device__ __forceinline__ void conv2w(const float* __restrict__ src,
                                       char* __restrict__ d0,
                                       char* __restrict__ d1) {
    int r = blockIdx.x, tid = threadIdx.x;
    int c0 = blockIdx.y * 1024 + tid * 4;
    float4 v = *(const float4*)(src + (size_t)r * WIDTH + c0);
    int kc = c0 >> 6, cl = c0 & 63;
    uint32_t off = (uint32_t)((r & 127) * 128 + cl * 2);
    off ^= (off >> 3) & 0x70;
    size_t base = ((size_t)((r >> 7) * (WIDTH / 64) + kc)) * TILEB + off;
    float f[4] = {v.x, v.y, v.z, v.w};
    unsigned short u0[4], u1[4];
    #pragma unroll
    for (int j = 0; j < 4; j++) {
        __nv_bfloat16 h0 = __float2bfloat16(f[j]);
        float r1 = f[j] - __bfloat162float(h0);
        u0[j] = __bfloat16_as_ushort(h0);
        u1[j] = __bfloat16_as_ushort(__float2bfloat16(r1));
    }
    ull p0 = (ull)u0[0] | ((ull)u0[1] << 16) | ((ull)u0[2] << 32) | ((ull)u0[3] << 48);
    ull p1 = (ull)u1[0] | ((ull)u1[1] << 16) | ((ull)u1[2] << 32) | ((ull)u1[3] << 48);
    *(ull*)(d0 + base) = p0;
    *(ull*)(d1 + base) = p1;
}

__global__ void __launch_bounds__(256) k_conv_x(const float* __restrict__ s)   { conv2w<DM>(s, (char*)g_xt0, (char*)g_xt1); }
__global__ void __launch_bounds__(256) k_conv_w1(const float* __restrict__ s)  { conv2w<DM>(s, (char*)g_w1t0, (char*)g_w1t1); }
__global__ void __launch_bounds__(256) k_conv_h()                              { conv2w<DM>(g_h, (char*)g_ht0, (char*)g_ht1); }
__global__ void __launch_bounds__(256) k_conv_wr2(const float* __restrict__ s) { conv2w<DM>(s, (char*)g_wr2t0, (char*)g_wr2t1); }
__global__ void __launch_bounds__(256) k_conv_w2(const float* __restrict__ s)  { conv2w<DFF>(s, (char*)g_w2t0, (char*)g_w2t1); }
__global__ void __launch_bounds__(256) k_conv_rho(const float* __restrict__ s) { conv2w<DH>(s, (char*)g_rt0, (char*)g_rt1); }

// ---------------- HMMA bf16 2-term GEMM, 256x128 CTA tile, 512 thr ----------
// C[256*by + m, 128*bx + n]; A spans two 128-row tile blocks. 2-stage x 96KB.
template <int NCH>
__device__ __forceinline__ void gemm2x(const ull* __restrict__ A0, const ull* __restrict__ A1,
                                       const ull* __restrict__ B0, const ull* __restrict__ B1,
                                       float* __restrict__ C, int ldc) {
    extern __shared__ char smem[];
    uint32_t sb = (s2u(smem) + 127u) & ~127u;
    const uint32_t STAGE = 6u * TILEB;

    int tid = threadIdx.x, lane = tid & 31, wid = tid >> 5;
    int wm = wid & 3, wn = wid >> 2;          // warp grid 4(m) x 4(n)
    int blkA = wm >> 1;                        // which 128-row tile block
    int bx = blockIdx.x, by = blockIdx.y;

    const ull* As[2] = {A0, A1};
    const ull* Bs[2] = {B0, B1};
    const int PA[3] = {0, 0, 1};
    const int PB[3] = {0, 1, 0};

    uint32_t rowA[4];
    {
        int ra = (wm & 1) * 64 + (lane & 15);
        #pragma unroll
        for (int mt = 0; mt < 4; mt++) {
            int rr = ra + mt * 16;
            rowA[mt] = (uint32_t)(rr * 128 + ((rr & 7) << 4));
        }
    }
    uint32_t acol = (uint32_t)((lane >> 4) * 16);
    uint32_t rowB[2];
    {
        int rb = wn * 32 + ((lane >> 4) << 3) + (lane & 7);
        #pragma unroll
        for (int n2 = 0; n2 < 2; n2++) {
            int rr = rb + n2 * 16;
            rowB[n2] = (uint32_t)(rr * 128 + ((rr & 7) << 4));
        }
    }
    uint32_t bcol = (uint32_t)(((lane >> 3) & 1) * 16);

    float acc[64];
    #pragma unroll
    for (int i = 0; i < 64; i++) acc[i] = 0.f;

    auto issue = [&](int kc, int s) {
        uint32_t dst = sb + (uint32_t)s * STAGE;
        #pragma unroll
        for (int t = 0; t < 2; t++) {
            #pragma unroll
            for (int b = 0; b < 2; b++) {
                const char* src = (const char*)As[t] +
                    ((size_t)(2 * by + b) * NCH + kc) * TILEB;
                uint32_t dt = dst + (uint32_t)(t * 2 + b) * TILEB;
                #pragma unroll
                for (int j = 0; j < 2; j++) {
                    uint32_t o = (uint32_t)(tid + j * 512) * 16;
                    cp16(dt + o, src + o);
                }
            }
        }
        #pragma unroll
        for (int t = 0; t < 2; t++) {
            const char* src = (const char*)Bs[t] + ((size_t)bx * NCH + kc) * TILEB;
            uint32_t dt = dst + (uint32_t)(4 + t) * TILEB;
            #pragma unroll
            for (int j = 0; j < 2; j++) {
                uint32_t o = (uint32_t)(tid + j * 512) * 16;
                cp16(dt + o, src + o);
            }
        }
        cp_commit();
    };

    issue(0, 0);
    issue(1, 1);

    for (int kc = 0; kc < NCH; kc++) {
        int s = kc & 1;
        if (kc == NCH - 1) cp_wait<0>(); else cp_wait<1>();
        __syncthreads();
        uint32_t stg = sb + (uint32_t)s * STAGE;
        #pragma unroll
        for (int p = 0; p < 3; p++) {
            uint32_t Ab = stg + (uint32_t)(PA[p] * 2 + blkA) * TILEB;
            uint32_t Bb = stg + (uint32_t)(4 + PB[p]) * TILEB;
            #pragma unroll
            for (int ks = 0; ks < 4; ks++) {
                uint32_t ka = (uint32_t)(ks * 32) + acol;
                uint32_t kb = (uint32_t)(ks * 32) + bcol;
                uint32_t bf[2][4], af[4][4];
                ldsm4(bf[0], (Bb + rowB[0]) ^ kb);
                ldsm4(bf[1], (Bb + rowB[1]) ^ kb);
                #pragma unroll
                for (int mt = 0; mt < 4; mt++)
                    ldsm4(af[mt], (Ab + rowA[mt]) ^ ka);
                #pragma unroll
                for (int mt = 0; mt < 4; mt++) {
                    #pragma unroll
                    for (int nt = 0; nt < 4; nt++)
                        mma16816(&acc[(mt * 4 + nt) * 4], af[mt],
                                 &bf[nt >> 1][(nt & 1) * 2]);
                }
            }
        }
        __syncthreads();
        if (kc + 2 < NCH) issue(kc + 2, s);
    }

    int rbase = by * 256 + wm * 64 + (lane >> 2);
    int cbase = bx * 128 + wn * 32 + (lane & 3) * 2;
    #pragma unroll
    for (int mt = 0; mt < 4; mt++) {
        #pragma unroll
        for (int nt = 0; nt < 4; nt++) {
            const float* a4 = &acc[(mt * 4 + nt) * 4];
            int row = rbase + mt * 16;
            int col = cbase + nt * 8;
            *(float2*)(C + (size_t)row * ldc + col)       = make_float2(a4[0], a4[1]);
            *(float2*)(C + (size_t)(row + 8) * ldc + col) = make_float2(a4[2], a4[3]);
        }
    }
}

__global__ void __launch_bounds__(512, 1) k_mm_z() {
    gemm2x<16>(g_xt0, g_xt1, g_w1t0, g_w1t1, g_z, DFF);
}
__global__ void __launch_bounds__(512, 1) k_mm_scores() {
    gemm2x<16>(g_ht0, g_ht1, g_wr2t0, g_wr2t1, g_scores, DFF);
}
__global__ void __launch_bounds__(512, 1) k_mm_out(float* __restrict__ out) {
    gemm2x<64>(g_at0, g_at1, g_w2t0, g_w2t1, out, DM);
}

// ---------------- top-256: linear-bin select, fully parallel tails ----------
__global__ void __launch_bounds__(256) k_topk(const float* __restrict__ Wr2) {
    __shared__ float r_sum[8], r_mx[8], r_mn[8];
    __shared__ int hist[4][256];
    __shared__ int sh_warp[8];
    __shared__ int sel[256];
    __shared__ int cand[256];
    __shared__ float cand_s[256];
    __shared__ int sh_cnt, sh_nc, sh_b;
    __shared__ float sh_base, sh_bw;

    int t = blockIdx.x, tid = threadIdx.x;
    int lane = tid & 31, w = tid >> 5;
    const float4* srow = (const float4*)(g_scores + (size_t)t * DFF);

    float4 v[4];
    float sum = 0.f, mx = -1e30f, mn = 1e30f;
    #pragma unroll
    for (int j = 0; j < 4; j++) {
        v[j] = srow[tid + j * 256];
        sum += (v[j].x + v[j].y) + (v[j].z + v[j].w);
        mx = fmaxf(mx, fmaxf(fmaxf(v[j].x, v[j].y), fmaxf(v[j].z, v[j].w)));
        mn = fminf(mn, fminf(fminf(v[j].x, v[j].y), fminf(v[j].z, v[j].w)));
    }
    #pragma unroll
    for (int o = 16; o; o >>= 1) {
        sum += __shfl_down_sync(0xffffffffu, sum, o);
        mx = fmaxf(mx, __shfl_down_sync(0xffffffffu, mx, o));
        mn = fminf(mn, __shfl_down_sync(0xffffffffu, mn, o));
    }
    if (lane == 0) { r_sum[w] = sum; r_mx[w] = mx; r_mn[w] = mn; }
    __syncthreads();
    float tsum = 0.f, tmx = -1e30f, tmn = 1e30f;
    #pragma unroll
    for (int i = 0; i < 8; i++) {
        tsum += r_sum[i];
        tmx = fmaxf(tmx, r_mx[i]);
        tmn = fminf(tmn, r_mn[i]);
    }
    float base = tsum * (1.0f / 4096.0f);
    int sub = lane & 3;

    for (int attempt = 0; attempt < 2; attempt++) {
        #pragma unroll
        for (int s = 0; s < 4; s++) hist[s][tid] = 0;
        __syncthreads();
        float inv_bw = 256.0f / (tmx - base);
        #pragma unroll
        for (int j = 0; j < 4; j++) {
            float s4[4] = {v[j].x, v[j].y, v[j].z, v[j].w};
            #pragma unroll
            for (int q = 0; q < 4; q++) {
                float s = s4[q];
                if (s > base) {
                    int b = (int)((s - base) * inv_bw);
                    atomicAdd(&hist[sub][b < 255 ? b : 255], 1);
                }
            }
        }
        __syncthreads();
        int hb = hist[0][255 - tid] + hist[1][255 - tid]
               + hist[2][255 - tid] + hist[3][255 - tid];
        int val = hb;
        #pragma unroll
        for (int o = 1; o < 32; o <<= 1) {
            int n = __shfl_up_sync(0xffffffffu, val, o);
            if (lane >= o) val += n;
        }
        if (lane == 31) sh_warp[w] = val;
        __syncthreads();
        int off = 0, tot = 0;
        #pragma unroll
        for (int ww = 0; ww < 8; ww++) {
            int sw = sh_warp[ww];
            if (ww < w) off += sw;
            tot += sw;
        }
        val += off;
        if (tot >= KSEL) {
            int excl = val - hb;
            if (val >= KSEL && excl < KSEL) {
                sh_b = 255 - tid;
                sh_base = base;
                sh_bw = (tmx - base) * (1.0f / 256.0f);
            }
            __syncthreads();
            break;
        }
        base = tmn;
        __syncthreads();
    }

    float binlo = sh_base + sh_b * sh_bw;
    float binhi = binlo + sh_bw;
    float hif = binhi + MARG, lof = binlo - MARG;

    if (tid == 0) { sh_cnt = 0; sh_nc = 0; }
    __syncthreads();
    #pragma unroll
    for (int j = 0; j < 4; j++) {
        float s4[4] = {v[j].x, v[j].y, v[j].z, v[j].w};
        #pragma unroll
        for (int q = 0; q < 4; q++) {
            float s = s4[q];
            int i = (tid + j * 256) * 4 + q;
            if (s > hif) {
                int p = atomicAdd(&sh_cnt, 1);
                if (p < 256) sel[p] = i;
            } else if (s > lof) {
                int p = atomicAdd(&sh_nc, 1);
                if (p < 256) cand[p] = i;
            }
        }
    }
    __syncthreads();
    int n_in = sh_cnt;
    int ncand = min(sh_nc, 256);
    int need = KSEL - n_in;

    const float4* hr = (const float4*)(g_h + (size_t)t * DM);
    for (int c = w; c < ncand; c += 8) {
        const float4* wr = (const float4*)(Wr2 + (size_t)cand[c] * DM);
        float acc = 0.f;
        #pragma unroll 4
        for (int k = lane; k < DM / 4; k += 32) {
            float4 w4 = wr[k];
            float4 h4 = hr[k];
            acc = fmaf(h4.x, w4.x, acc);
            acc = fmaf(h4.y, w4.y, acc);
            acc = fmaf(h4.z, w4.z, acc);
            acc = fmaf(h4.w, w4.w, acc);
        }
        #pragma unroll
        for (int o = 16; o; o >>= 1) acc += __shfl_down_sync(0xffffffffu, acc, o);
        if (lane == 0) cand_s[c] = acc;
    }
    __syncthreads();

    if (w == 0) {
        for (int c = lane; c < ncand; c += 32) {
            float sc = cand_s[c];
            int ic = cand[c];
            int rank = 0;
            for (int j = 0; j < ncand; j++) {
                float sj = cand_s[j];
                rank += (sj > sc || (sj == sc && cand[j] < ic)) ? 1 : 0;
            }
            if (rank < need) sel[n_in + rank] = ic;
        }
    }
    __syncthreads();

    int i = sel[tid];
    g_idx[(size_t)t * KSEL + tid] = i;
    float z = g_z[(size_t)t * DFF + i];
    g_asel[(size_t)t * KSEL + tid] = gelu_f(z);
}

// ---------------- DS stage 1 ------------------------------------------------
__global__ void __launch_bounds__(256) k_ds1(
    const float* __restrict__ phi1_w, const float* __restrict__ phi1_b,
    const float* __restrict__ ln1w,   const float* __restrict__ ln1b,
    const float* __restrict__ phi2_w, const float* __restrict__ phi2_b,
    const float* __restrict__ ln2w,   const float* __restrict__ ln2b) {
    extern __shared__ char dstage[];
    __shared__ __align__(8) float s_p1w[DH2], s_p1b[DH2], s_l1w[DH2], s_l1b[DH2];
    __shared__ __align__(8) float s_p2w[DH * DH2], s_p2b[DH], s_l2w[DH], s_l2b[DH];
    __shared__ float s_wsum[8][DH];
    __shared__ float s_ctx[DH];

    int t = blockIdx.x, tid = threadIdx.x;
    if (tid < DH2) {
        s_p1w[tid] = phi1_w[tid]; s_p1b[tid] = phi1_b[tid];
        s_l1w[tid] = ln1w[tid];   s_l1b[tid] = ln1b[tid];
    }
    if (tid < DH) {
        s_p2b[tid] = phi2_b[tid]; s_l2w[tid] = ln2w[tid]; s_l2b[tid] = ln2b[tid];
    }
    for (int i = tid; i < DH * DH2; i += 256) s_p2w[i] = phi2_w[i];
    __syncthreads();

    float a = g_asel[(size_t)t * KSEL + tid];

    float e1[DH2];
    float mu = 0.f;
    #pragma unroll
    for (int j = 0; j < DH2; j++) { e1[j] = fmaf(a, s_p1w[j], s_p1b[j]); mu += e1[j]; }
    mu *= (1.0f / DH2);
    float var = 0.f;
    #pragma unroll
    for (int j = 0; j < DH2; j++) { float d = e1[j] - mu; var += d * d; }
    float inv = rsqrtf(var * (1.0f / DH2) + 1e-5f);
    #pragma unroll
    for (int j = 0; j < DH2; j++)
        e1[j] = gelu_f((e1[j] - mu) * inv * s_l1w[j] + s_l1b[j]);

    ull e1p[DH2 / 2];
    #pragma unroll
    for (int j = 0; j < DH2 / 2; j++) e1p[j] = pack2(e1[2 * j], e1[2 * j + 1]);

    float e2[DH];
    #pragma unroll 4
    for (int h = 0; h < DH; h++) {
        const ull* wr = (const ull*)&s_p2w[h * DH2];
        ull a0 = 0ull, a1 = 0ull;
        #pragma unroll
        for (int j = 0; j < DH2 / 2; j += 2) {
            a0 = ffma2(e1p[j + 0], wr[j + 0], a0);
            a1 = ffma2(e1p[j + 1], wr[j + 1], a1);
        }
        float l0, h0, l1, h1;
        unpack2(a0, l0, h0); unpack2(a1, l1, h1);
        e2[h] = ((l0 + h0) + (l1 + h1)) + s_p2b[h];
    }
    float mu2 = 0.f;
    #pragma unroll
    for (int h = 0; h < DH; h++) mu2 += e2[h];
    mu2 *= (1.0f / DH);
    float var2 = 0.f;
    #pragma unroll
    for (int h = 0; h < DH; h++) { float d = e2[h] - mu2; var2 += d * d; }
    float inv2 = rsqrtf(var2 * (1.0f / DH) + 1e-5f);
    #pragma unroll
    for (int h = 0; h < DH; h++)
        e2[h] = (e2[h] - mu2) * inv2 * s_l2w[h] + s_l2b[h];

    int lane = tid & 31, w = tid >> 5;
    #pragma unroll
    for (int h = 0; h < DH; h++) {
        float v = e2[h];
        v += __shfl_down_sync(0xffffffffu, v, 16);
        v += __shfl_down_sync(0xffffffffu, v, 8);
        v += __shfl_down_sync(0xffffffffu, v, 4);
        v += __shfl_down_sync(0xffffffffu, v, 2);
        v += __shfl_down_sync(0xffffffffu, v, 1);
        if (lane == 0) s_wsum[w][h] = v;
    }
    __syncthreads();
    if (tid < DH) {
        float s = 0.f;
        #pragma unroll
        for (int ww = 0; ww < 8; ww++) s += s_wsum[ww][tid];
        s_ctx[tid] = s * (1.0f / KSEL);
    }
    __syncthreads();
    #pragma unroll
    for (int h = 0; h < DH; h++) e2[h] += s_ctx[h];

    int til = tid >> 7;
    uint32_t rbyte = (uint32_t)((tid & 127) * 128);
    #pragma unroll
    for (int j = 0; j < 16; j++) {
        unsigned short u0[4], u1[4];
        #pragma unroll
        for (int q = 0; q < 4; q++) {
            float f = e2[j * 4 + q];
            __nv_bfloat16 h0 = __float2bfloat16(f);
            u0[q] = __bfloat16_as_ushort(h0);
            u1[q] = __bfloat16_as_ushort(__float2bfloat16(f - __bfloat162float(h0)));
        }
        uint32_t off = rbyte + j * 8;
        off ^= (off >> 3) & 0x70;
        *(ull*)(dstage + til * TILEB + off) =
            (ull)u0[0] | ((ull)u0[1] << 16) | ((ull)u0[2] << 32) | ((ull)u0[3] << 48);
        *(ull*)(dstage + 2 * TILEB + til * TILEB + off) =
            (ull)u1[0] | ((ull)u1[1] << 16) | ((ull)u1[2] << 32) | ((ull)u1[3] << 48);
    }
    __syncthreads();
    const float4* ssrc = (const float4*)dstage;
    float4* d0 = (float4*)((char*)g_ct0 + (size_t)(2 * t) * TILEB);
    float4* d1 = (float4*)((char*)g_ct1 + (size_t)(2 * t) * TILEB);
    #pragma unroll
    for (int i = 0; i < 8; i++) d0[tid + i * 256] = ssrc[tid + i * 256];
    #pragma unroll
    for (int i = 0; i < 8; i++) d1[tid + i * 256] = ssrc[2048 + tid + i * 256];
}

// ---------------- DS stage 2 ------------------------------------------------
__global__ void __launch_bounds__(256, 1) k_ds2(const float* __restrict__ rho1_b_,
                                                const float* __restrict__ rho2_w_,
                                                const float* __restrict__ rho2_b_) {
    extern __shared__ char smem[];
    uint32_t sb = (s2u(smem) + 127u) & ~127u;
    __shared__ float s_man[128];
    __shared__ float s_r1b[DR], s_r2w[DR];

    int tid = threadIdx.x, lane = tid & 31, wid = tid >> 5;
    int wm = wid & 1, wn = wid >> 1;
    int bb = blockIdx.x;
    if (tid < DR) { s_r1b[tid] = rho1_b_[tid]; s_r2w[tid] = rho2_w_[tid]; }
    if (tid < 128) s_man[tid] = 0.f;
    float r2b = rho2_b_[0];

    {
        const char* a0 = (const char*)g_ct0 + (size_t)bb * TILEB;
        const char* a1 = (const char*)g_ct1 + (size_t)bb * TILEB;
        #pragma unroll
        for (int j = 0; j < 4; j++) {
            uint32_t o = (uint32_t)(tid + j * 256) * 16;
            cp16(sb + 0 * TILEB + o, a0 + o);
            cp16(sb + 1 * TILEB + o, a1 + o);
            cp16(sb + 2 * TILEB + o, (const char*)g_rt0 + o);
            cp16(sb + 3 * TILEB + o, (const char*)g_rt1 + o);
        }
        cp_commit();
    }

    uint32_t rowA[4];
    {
        int ra = wm * 64 + (lane & 15);
        #pragma unroll
        for (int mt = 0; mt < 4; mt++) {
            int rr = ra + mt * 16;
            rowA[mt] = (uint32_t)(rr * 128 + ((rr & 7) << 4));
        }
    }
    uint32_t acol = (uint32_t)((lane >> 4) * 16);
    uint32_t rowB[2];
    {
        int rb = wn * 32 + ((lane >> 4) << 3) + (lane & 7);
        #pragma unroll
        for (int n2 = 0; n2 < 2; n2++) {
            int rr = rb + n2 * 16;
            rowB[n2] = (uint32_t)(rr * 128 + ((rr & 7) << 4));
        }
    }
    uint32_t bcol = (uint32_t)(((lane >> 3) & 1) * 16);

    float acc[64];
    #pragma unroll
    for (int i = 0; i < 64; i++) acc[i] = 0.f;

    cp_wait<0>();
    __syncthreads();

    const int PA[3] = {0, 0, 1};
    const int PB[3] = {0, 1, 0};
    #pragma unroll
    for (int p = 0; p < 3; p++) {
        uint32_t Ab = sb + (uint32_t)PA[p] * TILEB;
        uint32_t Bb = sb + (uint32_t)(2 + PB[p]) * TILEB;
        #pragma unroll
        for (int ks = 0; ks < 4; ks++) {
            uint32_t ka = (uint32_t)(ks * 32) + acol;
            uint32_t kb = (uint32_t)(ks * 32) + bcol;
            uint32_t bf[2][4], af[4][4];
            ldsm4(bf[0], (Bb + rowB[0]) ^ kb);
            ldsm4(bf[1], (Bb + rowB[1]) ^ kb);
            #pragma unroll
            for (int mt = 0; mt < 4; mt++)
                ldsm4(af[mt], (Ab + rowA[mt]) ^ ka);
            #pragma unroll
            for (int mt = 0; mt < 4; mt++) {
                #pragma unroll
                for (int nt = 0; nt < 4; nt++)
                    mma16816(&acc[(mt * 4 + nt) * 4], af[mt],
                             &bf[nt >> 1][(nt & 1) * 2]);
            }
        }
    }

    int rloc = wm * 64 + (lane >> 2);
    int cb = wn * 32 + (lane & 3) * 2;
    #pragma unroll
    for (int mt = 0; mt < 4; mt++) {
        #pragma unroll
        for (int hh = 0; hh < 2; hh++) {
            float v = 0.f;
            #pragma unroll
            for (int nt = 0; nt < 4; nt++) {
                int c0 = cb + nt * 8;
                const float* a4 = &acc[(mt * 4 + nt) * 4 + hh * 2];
                v = fmaf(s_r2w[c0],     gelu_f(a4[0] + s_r1b[c0]),     v);
                v = fmaf(s_r2w[c0 + 1], gelu_f(a4[1] + s_r1b[c0 + 1]), v);
            }
            v += __shfl_xor_sync(0xffffffffu, v, 1);
            v += __shfl_xor_sync(0xffffffffu, v, 2);
            if ((lane & 3) == 0)
                atomicAdd(&s_man[rloc + mt * 16 + hh * 8], v);
        }
    }
    __syncthreads();

    if (tid < 128) {
        float man = s_man[tid] + r2b;
        int rg = bb * 128 + tid;
        int t = rg >> 8;
        int i = g_idx[rg];
        __nv_bfloat16 m0 = __float2bfloat16(man);
        __nv_bfloat16 m1 = __float2bfloat16(man - __bfloat162float(m0));
        int kc = i >> 6, cl = i & 63;
        uint32_t off = (uint32_t)((t & 127) * 128 + cl * 2);
        off ^= (off >> 3) & 0x70;
        size_t base = ((size_t)((t >> 7) * (DFF / 64) + kc)) * TILEB + off;
        *(unsigned short*)((char*)g_at0 + base) = __bfloat16_as_ushort(m0);
        *(unsigned short*)((char*)g_at1 + base) = __bfloat16_as_ushort(m1);
    }
}

// ---------------- launch ----------------------------------------------------
extern "C" void kernel_launch(void* const* d_in, const int* in_sizes, int n_in,
                              void* d_out, int out_size) {
    const float* x      = (const float*)d_in[0];
    const float* W1     = (const float*)d_in[1];
    const float* W2     = (const float*)d_in[2];
    const float* Wr1    = (const float*)d_in[3];
    const float* Wr2    = (const float*)d_in[4];
    const float* ln_w   = (const float*)d_in[5];
    const float* ln_b   = (const float*)d_in[6];
    const float* phi1_w = (const float*)d_in[7];
    const float* phi1_b = (const float*)d_in[8];
    const float* pl1w   = (const float*)d_in[9];
    const float* pl1b   = (const float*)d_in[10];
    const float* phi2_w = (const float*)d_in[11];
    const float* phi2_b = (const float*)d_in[12];
    const float* pl2w   = (const float*)d_in[13];
    const float* pl2b   = (const float*)d_in[14];
    const float* rho1_w = (const float*)d_in[15];
    const float* rho1_b = (const float*)d_in[16];
    const float* rho2_w = (const float*)d_in[17];
    const float* rho2_b = (const float*)d_in[18];
    float* out = (float*)d_out;

    const int smem2 = 256 + 2 * 6 * TILEB;  // 196864
    const int smem1 = 256 + 4 * TILEB;      // 65792
    const int smemd = 4 * TILEB;            // 65536
    cudaFuncSetAttribute(k_mm_z,      cudaFuncAttributeMaxDynamicSharedMemorySize, smem2);
    cudaFuncSetAttribute(k_mm_scores, cudaFuncAttributeMaxDynamicSharedMemorySize, smem2);
    cudaFuncSetAttribute(k_mm_out,    cudaFuncAttributeMaxDynamicSharedMemorySize, smem2);
    cudaFuncSetAttribute(k_ds2,       cudaFuncAttributeMaxDynamicSharedMemorySize, smem1);
    cudaFuncSetAttribute(k_ds1,       cudaFuncAttributeMaxDynamicSharedMemorySize, smemd);

    k_conv_w2<<<dim3(DM, DFF / 1024), 256>>>(W2);
    k_conv_x<<<T_TOK, 256>>>(x);
    k_conv_w1<<<DFF, 256>>>(W1);
    k_conv_wr2<<<DFF, 256>>>(Wr2);
    k_ln<<<T_TOK, 256>>>(x, ln_w, ln_b);
    k_mm_z<<<dim3(DFF / 128, T_TOK / 256), 512, smem2>>>();

    k_gemm_router1<<<dim3(DM / 128, T_TOK / 128), 256>>>(Wr1);
    k_conv_h<<<T_TOK, 256>>>();
    k_mm_scores<<<dim3(DFF / 128, T_TOK / 256), 512, smem2>>>();
    k_conv_rho<<<DR, 16>>>(rho1_w);
    k_topk<<<T_TOK, 256>>>(Wr2);

    k_ds1<<<T_TOK, 256, smemd>>>(phi1_w, phi1_b, pl1w, pl1b,
                                 phi2_w, phi2_b, pl2w, pl2b);
    k_ds2<<<(T_TOK * KSEL) / 128, 256, smem1>>>(rho1_b, rho2_w, rho2_b);

    k_mm_out<<<dim3(DM / 128, T_TOK / 256), 512, smem2>>>(out);
}

// round 15
// speedup vs baseline: 1.1814x; 1.1814x over previous
#include <cuda_runtime.h>
#include <cuda_bf16.h>
#include <cstdint>

#define T_TOK 4096
#define DM    1024
#define DFF   4096
#define KSEL  256
#define DH    64
#define DH2   32
#define DR    128
#define TILEB 16384
#define MARG  4e-4f

typedef unsigned long long ull;

__device__ float g_xn[(size_t)T_TOK * DM];
__device__ float g_h[(size_t)T_TOK * DM];
__device__ float g_scores[(size_t)T_TOK * DFF];
__device__ float g_z[(size_t)T_TOK * DFF];
__device__ float g_asel[(size_t)T_TOK * KSEL];
__device__ int   g_idx[(size_t)T_TOK * KSEL];

__device__ ull g_xt0[(size_t)T_TOK * DM / 4],  g_xt1[(size_t)T_TOK * DM / 4];
__device__ ull g_w1t0[(size_t)DFF * DM / 4],   g_w1t1[(size_t)DFF * DM / 4];
__device__ ull g_ht0[(size_t)T_TOK * DM / 4],  g_ht1[(size_t)T_TOK * DM / 4];
__device__ ull g_wr2t0[(size_t)DFF * DM / 4],  g_wr2t1[(size_t)DFF * DM / 4];
__device__ ull g_at0[(size_t)T_TOK * DFF / 4], g_at1[(size_t)T_TOK * DFF / 4];   // zero-init at load
__device__ ull g_w2t0[(size_t)DM * DFF / 4],   g_w2t1[(size_t)DM * DFF / 4];
__device__ ull g_ct0[(size_t)T_TOK * KSEL * DH / 4], g_ct1[(size_t)T_TOK * KSEL * DH / 4];
__device__ ull g_rt0[TILEB / 8], g_rt1[TILEB / 8];

__device__ __forceinline__ float gelu_f(float x) {
    return 0.5f * x * (1.0f + erff(x * 0.7071067811865475f));
}
__device__ __forceinline__ ull pack2(float lo, float hi) {
    ull r; asm("mov.b64 %0, {%1,%2};" : "=l"(r) : "f"(lo), "f"(hi)); return r;
}
__device__ __forceinline__ void unpack2(ull v, float &lo, float &hi) {
    asm("mov.b64 {%0,%1}, %2;" : "=f"(lo), "=f"(hi) : "l"(v));
}
__device__ __forceinline__ ull ffma2(ull a, ull b, ull c) {
    ull d; asm("fma.rn.f32x2 %0, %1, %2, %3;" : "=l"(d) : "l"(a), "l"(b), "l"(c));
    return d;
}
__device__ __forceinline__ uint32_t s2u(const void* p) {
    uint32_t a;
    asm("{ .reg .u64 t; cvta.to.shared.u64 t, %1; cvt.u32.u64 %0, t; }" : "=r"(a) : "l"(p));
    return a;
}
__device__ __forceinline__ void cp16(uint32_t d, const void* s) {
    asm volatile("cp.async.cg.shared.global [%0], [%1], 16;" :: "r"(d), "l"(s) : "memory");
}
__device__ __forceinline__ void cp_commit() {
    asm volatile("cp.async.commit_group;" ::: "memory");
}
template <int N>
__device__ __forceinline__ void cp_wait() {
    asm volatile("cp.async.wait_group %0;" :: "n"(N) : "memory");
}
__device__ __forceinline__ void ldsm4(uint32_t* r, uint32_t addr) {
    asm volatile("ldmatrix.sync.aligned.m8n8.x4.shared.b16 {%0,%1,%2,%3}, [%4];"
                 : "=r"(r[0]), "=r"(r[1]), "=r"(r[2]), "=r"(r[3]) : "r"(addr));
}
__device__ __forceinline__ void mma16816(float* d, const uint32_t* a, const uint32_t* b) {
    asm volatile(
        "mma.sync.aligned.m16n8k16.row.col.f32.bf16.bf16.f32 "
        "{%0,%1,%2,%3}, {%4,%5,%6,%7}, {%8,%9}, {%0,%1,%2,%3};"
        : "+f"(d[0]), "+f"(d[1]), "+f"(d[2]), "+f"(d[3])
        : "r"(a[0]), "r"(a[1]), "r"(a[2]), "r"(a[3]), "r"(b[0]), "r"(b[1]));
}

// ---------------- layernorm -------------------------------------------------
__global__ void __launch_bounds__(256) k_ln(const float* __restrict__ x,
                                            const float* __restrict__ w,
                                            const float* __restrict__ b) {
    __shared__ float red[8];
    int t = blockIdx.x, tid = threadIdx.x;
    float4 v = ((const float4*)(x + (size_t)t * DM))[tid];
    float s = v.x + v.y + v.z + v.w;
    #pragma unroll
    for (int o = 16; o; o >>= 1) s += __shfl_down_sync(0xffffffffu, s, o);
    if ((tid & 31) == 0) red[tid >> 5] = s;
    __syncthreads();
    float tot = 0.f;
    #pragma unroll
    for (int i = 0; i < 8; i++) tot += red[i];
    float mu = tot * (1.0f / DM);
    __syncthreads();
    float dx = v.x - mu, dy = v.y - mu, dz = v.z - mu, dw = v.w - mu;
    float q = dx * dx + dy * dy + dz * dz + dw * dw;
    #pragma unroll
    for (int o = 16; o; o >>= 1) q += __shfl_down_sync(0xffffffffu, q, o);
    if ((tid & 31) == 0) red[tid >> 5] = q;
    __syncthreads();
    float vt = 0.f;
    #pragma unroll
    for (int i = 0; i < 8; i++) vt += red[i];
    float inv = rsqrtf(vt * (1.0f / DM) + 1e-5f);
    float4 wv = ((const float4*)w)[tid];
    float4 bv = ((const float4*)b)[tid];
    float4 o;
    o.x = dx * inv * wv.x + bv.x;
    o.y = dy * inv * wv.y + bv.y;
    o.z = dz * inv * wv.z + bv.z;
    o.w = dw * inv * wv.w + bv.w;
    ((float4*)(g_xn + (size_t)t * DM))[tid] = o;
}

// ---------------- fp32 FFMA2 GEMM, B-skewed (bit-exact vs R1) ---------------
__device__ __forceinline__ void gemm_core(const float* __restrict__ A,
                                          const float* __restrict__ B,
                                          float* __restrict__ C,
                                          int N, bool do_gelu) {
    const int K = 1024;
    __shared__ float As[8][128];
    __shared__ float Bs[8][160];
    int tid = threadIdx.x;
    int m0 = blockIdx.y * 128, n0 = blockIdx.x * 128;
    int lr = tid >> 1;
    int lc = (tid & 1) * 4;
    const float* Ag = A + (size_t)(m0 + lr) * K + lc;
    const float* Bg = B + (size_t)(n0 + lr) * K + lc;
    int tx = tid & 15, ty = tid >> 4;
    int mo = ty * 8, no = tx * 8;
    int lrs = lr + ((lr >> 3) << 1);
    int nos = no + ((no >> 3) << 1);

    ull acc[32];
    #pragma unroll
    for (int i = 0; i < 32; i++) acc[i] = 0ull;

    float4 a4 = *(const float4*)Ag;
    float4 b4 = *(const float4*)Bg;

    #pragma unroll 1
    for (int kt = 0; kt < K / 8; kt++) {
        As[lc + 0][lr] = a4.x; As[lc + 1][lr] = a4.y;
        As[lc + 2][lr] = a4.z; As[lc + 3][lr] = a4.w;
        Bs[lc + 0][lrs] = b4.x; Bs[lc + 1][lrs] = b4.y;
        Bs[lc + 2][lrs] = b4.z; Bs[lc + 3][lrs] = b4.w;
        __syncthreads();
        if (kt + 1 < K / 8) {
            a4 = *(const float4*)(Ag + (kt + 1) * 8);
            b4 = *(const float4*)(Bg + (kt + 1) * 8);
        }
        #pragma unroll
        for (int k = 0; k < 8; k++) {
            float4 aA = *(const float4*)&As[k][mo];
            float4 aB = *(const float4*)&As[k][mo + 4];
            const ull* bp = (const ull*)&Bs[k][nos];
            ull b0 = bp[0], b1 = bp[1], b2 = bp[2], b3 = bp[3];
            float am[8] = {aA.x, aA.y, aA.z, aA.w, aB.x, aB.y, aB.z, aB.w};
            #pragma unroll
            for (int i = 0; i < 8; i++) {
                ull ap = pack2(am[i], am[i]);
                acc[i * 4 + 0] = ffma2(ap, b0, acc[i * 4 + 0]);
                acc[i * 4 + 1] = ffma2(ap, b1, acc[i * 4 + 1]);
                acc[i * 4 + 2] = ffma2(ap, b2, acc[i * 4 + 2]);
                acc[i * 4 + 3] = ffma2(ap, b3, acc[i * 4 + 3]);
            }
        }
        __syncthreads();
    }
    #pragma unroll
    for (int i = 0; i < 8; i++) {
        float* crow = C + (size_t)(m0 + mo + i) * N + n0 + no;
        #pragma unroll
        for (int p = 0; p < 4; p++) {
            float lo, hi;
            unpack2(acc[i * 4 + p], lo, hi);
            if (do_gelu) { lo = gelu_f(lo); hi = gelu_f(hi); }
            crow[2 * p]     = lo;
            crow[2 * p + 1] = hi;
        }
    }
}

__global__ void __launch_bounds__(256, 2) k_gemm_router1(const float* __restrict__ Wr1) {
    gemm_core(g_xn, Wr1, g_h, DM, true);
}

// ---------------- fp32 -> 2 bf16 term tiles ---------------------------------
template <int WIDTH>
__device__ __forceinline__ void conv2w(const float* __restrict__ src,
                                       char* __restrict__ d0,
                                       char* __restrict__ d1) {
    int r = blockIdx.x, tid = threadIdx.x;
    int c0 = blockIdx.y * 1024 + tid * 4;
    float4 v = *(const float4*)(src + (size_t)r * WIDTH + c0);
    int kc = c0 >> 6, cl = c0 & 63;
    uint32_t off = (uint32_t)((r & 127) * 128 + cl * 2);
    off ^= (off >> 3) & 0x70;
    size_t base = ((size_t)((r >> 7) * (WIDTH / 64) + kc)) * TILEB + off;
    float f[4] = {v.x, v.y, v.z, v.w};
    unsigned short u0[4], u1[4];
    #pragma unroll
    for (int j = 0; j < 4; j++) {
        __nv_bfloat16 h0 = __float2bfloat16(f[j]);
        float r1 = f[j] - __bfloat162float(h0);
        u0[j] = __bfloat16_as_ushort(h0);
        u1[j] = __bfloat16_as_ushort(__float2bfloat16(r1));
    }
    ull p0 = (ull)u0[0] | ((ull)u0[1] << 16) | ((ull)u0[2] << 32) | ((ull)u0[3] << 48);
    ull p1 = (ull)u1[0] | ((ull)u1[1] << 16) | ((ull)u1[2] << 32) | ((ull)u1[3] << 48);
    *(ull*)(d0 + base) = p0;
    *(ull*)(d1 + base) = p1;
}

__global__ void __launch_bounds__(256) k_conv_x(const float* __restrict__ s)   { conv2w<DM>(s, (char*)g_xt0, (char*)g_xt1); }
__global__ void __launch_bounds__(256) k_conv_w1(const float* __restrict__ s)  { conv2w<DM>(s, (char*)g_w1t0, (char*)g_w1t1); }
__global__ void __launch_bounds__(256) k_conv_h()                              { conv2w<DM>(g_h, (char*)g_ht0, (char*)g_ht1); }
__global__ void __launch_bounds__(256) k_conv_wr2(const float* __restrict__ s) { conv2w<DM>(s, (char*)g_wr2t0, (char*)g_wr2t1); }
__global__ void __launch_bounds__(256) k_conv_w2(const float* __restrict__ s)  { conv2w<DFF>(s, (char*)g_w2t0, (char*)g_w2t1); }
__global__ void __launch_bounds__(256) k_conv_rho(const float* __restrict__ s) { conv2w<DH>(s, (char*)g_rt0, (char*)g_rt1); }

// ---------------- HMMA bf16 2-term GEMM (3 products, 3-stage) ---------------
// ks-outer mainloop: fragments loaded once per ks, shared across products.
template <int NCH>
__device__ __forceinline__ void gemm2t(const ull* __restrict__ A0, const ull* __restrict__ A1,
                                       const ull* __restrict__ B0, const ull* __restrict__ B1,
                                       float* __restrict__ C, int ldc) {
    extern __shared__ char smem[];
    uint32_t sb = (s2u(smem) + 127u) & ~127u;
    const uint32_t STAGE = 4u * TILEB;

    int tid = threadIdx.x, lane = tid & 31, wid = tid >> 5;
    int wm = wid & 1, wn = wid >> 1;
    int bx = blockIdx.x, by = blockIdx.y;

    const ull* As[2] = {A0, A1};
    const ull* Bs[2] = {B0, B1};

    uint32_t rowA[4];
    {
        int ra = wm * 64 + (lane & 15);
        #pragma unroll
        for (int mt = 0; mt < 4; mt++) {
            int rr = ra + mt * 16;
            rowA[mt] = (uint32_t)(rr * 128 + ((rr & 7) << 4));
        }
    }
    uint32_t acol = (uint32_t)((lane >> 4) * 16);
    uint32_t rowB[2];
    {
        int rb = wn * 32 + ((lane >> 4) << 3) + (lane & 7);
        #pragma unroll
        for (int n2 = 0; n2 < 2; n2++) {
            int rr = rb + n2 * 16;
            rowB[n2] = (uint32_t)(rr * 128 + ((rr & 7) << 4));
        }
    }
    uint32_t bcol = (uint32_t)(((lane >> 3) & 1) * 16);

    float acc[64];
    #pragma unroll
    for (int i = 0; i < 64; i++) acc[i] = 0.f;

    auto issue = [&](int kc, int s) {
        uint32_t dst = sb + (uint32_t)s * STAGE;
        #pragma unroll
        for (int t = 0; t < 2; t++) {
            const char* src = (const char*)As[t] + ((size_t)by * NCH + kc) * TILEB;
            #pragma unroll
            for (int j = 0; j < 4; j++) {
                uint32_t o = (uint32_t)(tid + j * 256) * 16;
                cp16(dst + (uint32_t)t * TILEB + o, src + o);
            }
        }
        #pragma unroll
        for (int t = 0; t < 2; t++) {
            const char* src = (const char*)Bs[t] + ((size_t)bx * NCH + kc) * TILEB;
            #pragma unroll
            for (int j = 0; j < 4; j++) {
                uint32_t o = (uint32_t)(tid + j * 256) * 16;
                cp16(dst + (uint32_t)(2 + t) * TILEB + o, src + o);
            }
        }
        cp_commit();
    };

    issue(0, 0);
    issue(1, 1);
    issue(2, 2);

    for (int kc = 0; kc < NCH; kc++) {
        int s = kc % 3;
        if (kc >= NCH - 1)      cp_wait<0>();
        else if (kc == NCH - 2) cp_wait<1>();
        else                    cp_wait<2>();
        __syncthreads();
        uint32_t stg = sb + (uint32_t)s * STAGE;
        #pragma unroll
        for (int ks = 0; ks < 4; ks++) {
            uint32_t ka = (uint32_t)(ks * 32) + acol;
            uint32_t kb = (uint32_t)(ks * 32) + bcol;
            uint32_t af[2][4][4], bf[2][2][4];
            #pragma unroll
            for (int tA = 0; tA < 2; tA++) {
                uint32_t Ab = stg + (uint32_t)tA * TILEB;
                #pragma unroll
                for (int mt = 0; mt < 4; mt++)
                    ldsm4(af[tA][mt], (Ab + rowA[mt]) ^ ka);
            }
            #pragma unroll
            for (int tB = 0; tB < 2; tB++) {
                uint32_t Bb = stg + (uint32_t)(2 + tB) * TILEB;
                ldsm4(bf[tB][0], (Bb + rowB[0]) ^ kb);
                ldsm4(bf[tB][1], (Bb + rowB[1]) ^ kb);
            }
            // products: A0*B0, A0*B1, A1*B0 (fragments reused from registers)
            #pragma unroll
            for (int mt = 0; mt < 4; mt++) {
                #pragma unroll
                for (int nt = 0; nt < 4; nt++)
                    mma16816(&acc[(mt * 4 + nt) * 4], af[0][mt],
                             &bf[0][nt >> 1][(nt & 1) * 2]);
            }
            #pragma unroll
            for (int mt = 0; mt < 4; mt++) {
                #pragma unroll
                for (int nt = 0; nt < 4; nt++)
                    mma16816(&acc[(mt * 4 + nt) * 4], af[0][mt],
                             &bf[1][nt >> 1][(nt & 1) * 2]);
            }
            #pragma unroll
            for (int mt = 0; mt < 4; mt++) {
                #pragma unroll
                for (int nt = 0; nt < 4; nt++)
                    mma16816(&acc[(mt * 4 + nt) * 4], af[1][mt],
                             &bf[0][nt >> 1][(nt & 1) * 2]);
            }
        }
        __syncthreads();
        if (kc + 3 < NCH) issue(kc + 3, (kc + 3) % 3);
    }

    int rbase = by * 128 + wm * 64 + (lane >> 2);
    int cbase = bx * 128 + wn * 32 + (lane & 3) * 2;
    #pragma unroll
    for (int mt = 0; mt < 4; mt++) {
        #pragma unroll
        for (int nt = 0; nt < 4; nt++) {
            const float* a4 = &acc[(mt * 4 + nt) * 4];
            int row = rbase + mt * 16;
            int col = cbase + nt * 8;
            *(float2*)(C + (size_t)row * ldc + col)       = make_float2(a4[0], a4[1]);
            *(float2*)(C + (size_t)(row + 8) * ldc + col) = make_float2(a4[2], a4[3]);
        }
    }
}

__global__ void __launch_bounds__(256, 1) k_mm_z() {
    gemm2t<16>(g_xt0, g_xt1, g_w1t0, g_w1t1, g_z, DFF);
}
__global__ void __launch_bounds__(256, 1) k_mm_scores() {
    gemm2t<16>(g_ht0, g_ht1, g_wr2t0, g_wr2t1, g_scores, DFF);
}
__global__ void __launch_bounds__(256, 1) k_mm_out(float* __restrict__ out) {
    gemm2t<64>(g_at0, g_at1, g_w2t0, g_w2t1, out, DM);
}

// ---------------- top-256: linear-bin select, fully parallel tails ----------
__global__ void __launch_bounds__(256) k_topk(const float* __restrict__ Wr2) {
    __shared__ float r_sum[8], r_mx[8], r_mn[8];
    __shared__ int hist[4][256];
    __shared__ int sh_warp[8];
    __shared__ int sel[256];
    __shared__ int cand[256];
    __shared__ float cand_s[256];
    __shared__ int sh_cnt, sh_nc, sh_b;
    __shared__ float sh_base, sh_bw;

    int t = blockIdx.x, tid = threadIdx.x;
    int lane = tid & 31, w = tid >> 5;
    const float4* srow = (const float4*)(g_scores + (size_t)t * DFF);

    float4 v[4];
    float sum = 0.f, mx = -1e30f, mn = 1e30f;
    #pragma unroll
    for (int j = 0; j < 4; j++) {
        v[j] = srow[tid + j * 256];
        sum += (v[j].x + v[j].y) + (v[j].z + v[j].w);
        mx = fmaxf(mx, fmaxf(fmaxf(v[j].x, v[j].y), fmaxf(v[j].z, v[j].w)));
        mn = fminf(mn, fminf(fminf(v[j].x, v[j].y), fminf(v[j].z, v[j].w)));
    }
    #pragma unroll
    for (int o = 16; o; o >>= 1) {
        sum += __shfl_down_sync(0xffffffffu, sum, o);
        mx = fmaxf(mx, __shfl_down_sync(0xffffffffu, mx, o));
        mn = fminf(mn, __shfl_down_sync(0xffffffffu, mn, o));
    }
    if (lane == 0) { r_sum[w] = sum; r_mx[w] = mx; r_mn[w] = mn; }
    __syncthreads();
    float tsum = 0.f, tmx = -1e30f, tmn = 1e30f;
    #pragma unroll
    for (int i = 0; i < 8; i++) {
        tsum += r_sum[i];
        tmx = fmaxf(tmx, r_mx[i]);
        tmn = fminf(tmn, r_mn[i]);
    }
    float base = tsum * (1.0f / 4096.0f);
    int sub = lane & 3;

    for (int attempt = 0; attempt < 2; attempt++) {
        #pragma unroll
        for (int s = 0; s < 4; s++) hist[s][tid] = 0;
        __syncthreads();
        float inv_bw = 256.0f / (tmx - base);
        #pragma unroll
        for (int j = 0; j < 4; j++) {
            float s4[4] = {v[j].x, v[j].y, v[j].z, v[j].w};
            #pragma unroll
            for (int q = 0; q < 4; q++) {
                float s = s4[q];
                if (s > base) {
                    int b = (int)((s - base) * inv_bw);
                    atomicAdd(&hist[sub][b < 255 ? b : 255], 1);
                }
            }
        }
        __syncthreads();
        int hb = hist[0][255 - tid] + hist[1][255 - tid]
               + hist[2][255 - tid] + hist[3][255 - tid];
        int val = hb;
        #pragma unroll
        for (int o = 1; o < 32; o <<= 1) {
            int n = __shfl_up_sync(0xffffffffu, val, o);
            if (lane >= o) val += n;
        }
        if (lane == 31) sh_warp[w] = val;
        __syncthreads();
        int off = 0, tot = 0;
        #pragma unroll
        for (int ww = 0; ww < 8; ww++) {
            int sw = sh_warp[ww];
            if (ww < w) off += sw;
            tot += sw;
        }
        val += off;
        if (tot >= KSEL) {
            int excl = val - hb;
            if (val >= KSEL && excl < KSEL) {
                sh_b = 255 - tid;
                sh_base = base;
                sh_bw = (tmx - base) * (1.0f / 256.0f);
            }
            __syncthreads();
            break;
        }
        base = tmn;
        __syncthreads();
    }

    float binlo = sh_base + sh_b * sh_bw;
    float binhi = binlo + sh_bw;
    float hif = binhi + MARG, lof = binlo - MARG;

    if (tid == 0) { sh_cnt = 0; sh_nc = 0; }
    __syncthreads();
    #pragma unroll
    for (int j = 0; j < 4; j++) {
        float s4[4] = {v[j].x, v[j].y, v[j].z, v[j].w};
        #pragma unroll
        for (int q = 0; q < 4; q++) {
            float s = s4[q];
            int i = (tid + j * 256) * 4 + q;
            if (s > hif) {
                int p = atomicAdd(&sh_cnt, 1);
                if (p < 256) sel[p] = i;
            } else if (s > lof) {
                int p = atomicAdd(&sh_nc, 1);
                if (p < 256) cand[p] = i;
            }
        }
    }
    __syncthreads();
    int n_in = sh_cnt;
    int ncand = min(sh_nc, 256);
    int need = KSEL - n_in;

    const float4* hr = (const float4*)(g_h + (size_t)t * DM);
    for (int c = w; c < ncand; c += 8) {
        const float4* wr = (const float4*)(Wr2 + (size_t)cand[c] * DM);
        float acc = 0.f;
        #pragma unroll 4
        for (int k = lane; k < DM / 4; k += 32) {
            float4 w4 = wr[k];
            float4 h4 = hr[k];
            acc = fmaf(h4.x, w4.x, acc);
            acc = fmaf(h4.y, w4.y, acc);
            acc = fmaf(h4.z, w4.z, acc);
            acc = fmaf(h4.w, w4.w, acc);
        }
        #pragma unroll
        for (int o = 16; o; o >>= 1) acc += __shfl_down_sync(0xffffffffu, acc, o);
        if (lane == 0) cand_s[c] = acc;
    }
    __syncthreads();

    if (w == 0) {
        for (int c = lane; c < ncand; c += 32) {
            float sc = cand_s[c];
            int ic = cand[c];
            int rank = 0;
            for (int j = 0; j < ncand; j++) {
                float sj = cand_s[j];
                rank += (sj > sc || (sj == sc && cand[j] < ic)) ? 1 : 0;
            }
            if (rank < need) sel[n_in + rank] = ic;
        }
    }
    __syncthreads();

    int i = sel[tid];
    g_idx[(size_t)t * KSEL + tid] = i;
    float z = g_z[(size_t)t * DFF + i];
    g_asel[(size_t)t * KSEL + tid] = gelu_f(z);
}

// ---------------- DS stage 1 ------------------------------------------------
__global__ void __launch_bounds__(256) k_ds1(
    const float* __restrict__ phi1_w, const float* __restrict__ phi1_b,
    const float* __restrict__ ln1w,   const float* __restrict__ ln1b,
    const float* __restrict__ phi2_w, const float* __restrict__ phi2_b,
    const float* __restrict__ ln2w,   const float* __restrict__ ln2b) {
    extern __shared__ char dstage[];
    __shared__ __align__(8) float s_p1w[DH2], s_p1b[DH2], s_l1w[DH2], s_l1b[DH2];
    __shared__ __align__(8) float s_p2w[DH * DH2], s_p2b[DH], s_l2w[DH], s_l2b[DH];
    __shared__ float s_wsum[8][DH];
    __shared__ float s_ctx[DH];

    int t = blockIdx.x, tid = threadIdx.x;
    if (tid < DH2) {
        s_p1w[tid] = phi1_w[tid]; s_p1b[tid] = phi1_b[tid];
        s_l1w[tid] = ln1w[tid];   s_l1b[tid] = ln1b[tid];
    }
    if (tid < DH) {
        s_p2b[tid] = phi2_b[tid]; s_l2w[tid] = ln2w[tid]; s_l2b[tid] = ln2b[tid];
    }
    for (int i = tid; i < DH * DH2; i += 256) s_p2w[i] = phi2_w[i];
    __syncthreads();

    float a = g_asel[(size_t)t * KSEL + tid];

    float e1[DH2];
    float mu = 0.f;
    #pragma unroll
    for (int j = 0; j < DH2; j++) { e1[j] = fmaf(a, s_p1w[j], s_p1b[j]); mu += e1[j]; }
    mu *= (1.0f / DH2);
    float var = 0.f;
    #pragma unroll
    for (int j = 0; j < DH2; j++) { float d = e1[j] - mu; var += d * d; }
    float inv = rsqrtf(var * (1.0f / DH2) + 1e-5f);
    #pragma unroll
    for (int j = 0; j < DH2; j++)
        e1[j] = gelu_f((e1[j] - mu) * inv * s_l1w[j] + s_l1b[j]);

    ull e1p[DH2 / 2];
    #pragma unroll
    for (int j = 0; j < DH2 / 2; j++) e1p[j] = pack2(e1[2 * j], e1[2 * j + 1]);

    float e2[DH];
    #pragma unroll 4
    for (int h = 0; h < DH; h++) {
        const ull* wr = (const ull*)&s_p2w[h * DH2];
        ull a0 = 0ull, a1 = 0ull;
        #pragma unroll
        for (int j = 0; j < DH2 / 2; j += 2) {
            a0 = ffma2(e1p[j + 0], wr[j + 0], a0);
            a1 = ffma2(e1p[j + 1], wr[j + 1], a1);
        }
        float l0, h0, l1, h1;
        unpack2(a0, l0, h0); unpack2(a1, l1, h1);
        e2[h] = ((l0 + h0) + (l1 + h1)) + s_p2b[h];
    }
    float mu2 = 0.f;
    #pragma unroll
    for (int h = 0; h < DH; h++) mu2 += e2[h];
    mu2 *= (1.0f / DH);
    float var2 = 0.f;
    #pragma unroll
    for (int h = 0; h < DH; h++) { float d = e2[h] - mu2; var2 += d * d; }
    float inv2 = rsqrtf(var2 * (1.0f / DH) + 1e-5f);
    #pragma unroll
    for (int h = 0; h < DH; h++)
        e2[h] = (e2[h] - mu2) * inv2 * s_l2w[h] + s_l2b[h];

    int lane = tid & 31, w = tid >> 5;
    #pragma unroll
    for (int h = 0; h < DH; h++) {
        float v = e2[h];
        v += __shfl_down_sync(0xffffffffu, v, 16);
        v += __shfl_down_sync(0xffffffffu, v, 8);
        v += __shfl_down_sync(0xffffffffu, v, 4);
        v += __shfl_down_sync(0xffffffffu, v, 2);
        v += __shfl_down_sync(0xffffffffu, v, 1);
        if (lane == 0) s_wsum[w][h] = v;
    }
    __syncthreads();
    if (tid < DH) {
        float s = 0.f;
        #pragma unroll
        for (int ww = 0; ww < 8; ww++) s += s_wsum[ww][tid];
        s_ctx[tid] = s * (1.0f / KSEL);
    }
    __syncthreads();
    #pragma unroll
    for (int h = 0; h < DH; h++) e2[h] += s_ctx[h];

    int til = tid >> 7;
    uint32_t rbyte = (uint32_t)((tid & 127) * 128);
    #pragma unroll
    for (int j = 0; j < 16; j++) {
        unsigned short u0[4], u1[4];
        #pragma unroll
        for (int q = 0; q < 4; q++) {
            float f = e2[j * 4 + q];
            __nv_bfloat16 h0 = __float2bfloat16(f);
            u0[q] = __bfloat16_as_ushort(h0);
            u1[q] = __bfloat16_as_ushort(__float2bfloat16(f - __bfloat162float(h0)));
        }
        uint32_t off = rbyte + j * 8;
        off ^= (off >> 3) & 0x70;
        *(ull*)(dstage + til * TILEB + off) =
            (ull)u0[0] | ((ull)u0[1] << 16) | ((ull)u0[2] << 32) | ((ull)u0[3] << 48);
        *(ull*)(dstage + 2 * TILEB + til * TILEB + off) =
            (ull)u1[0] | ((ull)u1[1] << 16) | ((ull)u1[2] << 32) | ((ull)u1[3] << 48);
    }
    __syncthreads();
    const float4* ssrc = (const float4*)dstage;
    float4* d0 = (float4*)((char*)g_ct0 + (size_t)(2 * t) * TILEB);
    float4* d1 = (float4*)((char*)g_ct1 + (size_t)(2 * t) * TILEB);
    #pragma unroll
    for (int i = 0; i < 8; i++) d0[tid + i * 256] = ssrc[tid + i * 256];
    #pragma unroll
    for (int i = 0; i < 8; i++) d1[tid + i * 256] = ssrc[2048 + tid + i * 256];
}

// ---------------- DS stage 2 ------------------------------------------------
__global__ void __launch_bounds__(256, 1) k_ds2(const float* __restrict__ rho1_b_,
                                                const float* __restrict__ rho2_w_,
                                                const float* __restrict__ rho2_b_) {
    extern __shared__ char smem[];
    uint32_t sb = (s2u(smem) + 127u) & ~127u;
    __shared__ float s_man[128];
    __shared__ float s_r1b[DR], s_r2w[DR];

    int tid = threadIdx.x, lane = tid & 31, wid = tid >> 5;
    int wm = wid & 1, wn = wid >> 1;
    int bb = blockIdx.x;
    if (tid < DR) { s_r1b[tid] = rho1_b_[tid]; s_r2w[tid] = rho2_w_[tid]; }
    if (tid < 128) s_man[tid] = 0.f;
    float r2b = rho2_b_[0];

    {
        const char* a0 = (const char*)g_ct0 + (size_t)bb * TILEB;
        const char* a1 = (const char*)g_ct1 + (size_t)bb * TILEB;
        #pragma unroll
        for (int j = 0; j < 4; j++) {
            uint32_t o = (uint32_t)(tid + j * 256) * 16;
            cp16(sb + 0 * TILEB + o, a0 + o);
            cp16(sb + 1 * TILEB + o, a1 + o);
            cp16(sb + 2 * TILEB + o, (const char*)g_rt0 + o);
            cp16(sb + 3 * TILEB + o, (const char*)g_rt1 + o);
        }
        cp_commit();
    }

    uint32_t rowA[4];
    {
        int ra = wm * 64 + (lane & 15);
        #pragma unroll
        for (int mt = 0; mt < 4; mt++) {
            int rr = ra + mt * 16;
            rowA[mt] = (uint32_t)(rr * 128 + ((rr & 7) << 4));
        }
    }
    uint32_t acol = (uint32_t)((lane >> 4) * 16);
    uint32_t rowB[2];
    {
        int rb = wn * 32 + ((lane >> 4) << 3) + (lane & 7);
        #pragma unroll
        for (int n2 = 0; n2 < 2; n2++) {
            int rr = rb + n2 * 16;
            rowB[n2] = (uint32_t)(rr * 128 + ((rr & 7) << 4));
        }
    }
    uint32_t bcol = (uint32_t)(((lane >> 3) & 1) * 16);

    float acc[64];
    #pragma unroll
    for (int i = 0; i < 64; i++) acc[i] = 0.f;

    cp_wait<0>();
    __syncthreads();

    #pragma unroll
    for (int ks = 0; ks < 4; ks++) {
        uint32_t ka = (uint32_t)(ks * 32) + acol;
        uint32_t kb = (uint32_t)(ks * 32) + bcol;
        uint32_t af[2][4][4], bf[2][2][4];
        #pragma unroll
        for (int tA = 0; tA < 2; tA++) {
            uint32_t Ab = sb + (uint32_t)tA * TILEB;
            #pragma unroll
            for (int mt = 0; mt < 4; mt++)
                ldsm4(af[tA][mt], (Ab + rowA[mt]) ^ ka);
        }
        #pragma unroll
        for (int tB = 0; tB < 2; tB++) {
            uint32_t Bb = sb + (uint32_t)(2 + tB) * TILEB;
            ldsm4(bf[tB][0], (Bb + rowB[0]) ^ kb);
            ldsm4(bf[tB][1], (Bb + rowB[1]) ^ kb);
        }
        #pragma unroll
        for (int mt = 0; mt < 4; mt++) {
            #pragma unroll
            for (int nt = 0; nt < 4; nt++)
                mma16816(&acc[(mt * 4 + nt) * 4], af[0][mt],
                         &bf[0][nt >> 1][(nt & 1) * 2]);
        }
        #pragma unroll
        for (int mt = 0; mt < 4; mt++) {
            #pragma unroll
            for (int nt = 0; nt < 4; nt++)
                mma16816(&acc[(mt * 4 + nt) * 4], af[0][mt],
                         &bf[1][nt >> 1][(nt & 1) * 2]);
        }
        #pragma unroll
        for (int mt = 0; mt < 4; mt++) {
            #pragma unroll
            for (int nt = 0; nt < 4; nt++)
                mma16816(&acc[(mt * 4 + nt) * 4], af[1][mt],
                         &bf[0][nt >> 1][(nt & 1) * 2]);
        }
    }

    int rloc = wm * 64 + (lane >> 2);
    int cb = wn * 32 + (lane & 3) * 2;
    #pragma unroll
    for (int mt = 0; mt < 4; mt++) {
        #pragma unroll
        for (int hh = 0; hh < 2; hh++) {
            float v = 0.f;
            #pragma unroll
            for (int nt = 0; nt < 4; nt++) {
                int c0 = cb + nt * 8;
                const float* a4 = &acc[(mt * 4 + nt) * 4 + hh * 2];
                v = fmaf(s_r2w[c0],     gelu_f(a4[0] + s_r1b[c0]),     v);
                v = fmaf(s_r2w[c0 + 1], gelu_f(a4[1] + s_r1b[c0 + 1]), v);
            }
            v += __shfl_xor_sync(0xffffffffu, v, 1);
            v += __shfl_xor_sync(0xffffffffu, v, 2);
            if ((lane & 3) == 0)
                atomicAdd(&s_man[rloc + mt * 16 + hh * 8], v);
        }
    }
    __syncthreads();

    if (tid < 128) {
        float man = s_man[tid] + r2b;
        int rg = bb * 128 + tid;
        int t = rg >> 8;
        int i = g_idx[rg];
        __nv_bfloat16 m0 = __float2bfloat16(man);
        __nv_bfloat16 m1 = __float2bfloat16(man - __bfloat162float(m0));
        int kc = i >> 6, cl = i & 63;
        uint32_t off = (uint32_t)((t & 127) * 128 + cl * 2);
        off ^= (off >> 3) & 0x70;
        size_t base = ((size_t)((t >> 7) * (DFF / 64) + kc)) * TILEB + off;
        *(unsigned short*)((char*)g_at0 + base) = __bfloat16_as_ushort(m0);
        *(unsigned short*)((char*)g_at1 + base) = __bfloat16_as_ushort(m1);
    }
}

// ---------------- launch ----------------------------------------------------
extern "C" void kernel_launch(void* const* d_in, const int* in_sizes, int n_in,
                              void* d_out, int out_size) {
    const float* x      = (const float*)d_in[0];
    const float* W1     = (const float*)d_in[1];
    const float* W2     = (const float*)d_in[2];
    const float* Wr1    = (const float*)d_in[3];
    const float* Wr2    = (const float*)d_in[4];
    const float* ln_w   = (const float*)d_in[5];
    const float* ln_b   = (const float*)d_in[6];
    const float* phi1_w = (const float*)d_in[7];
    const float* phi1_b = (const float*)d_in[8];
    const float* pl1w   = (const float*)d_in[9];
    const float* pl1b   = (const float*)d_in[10];
    const float* phi2_w = (const float*)d_in[11];
    const float* phi2_b = (const float*)d_in[12];
    const float* pl2w   = (const float*)d_in[13];
    const float* pl2b   = (const float*)d_in[14];
    const float* rho1_w = (const float*)d_in[15];
    const float* rho1_b = (const float*)d_in[16];
    const float* rho2_w = (const float*)d_in[17];
    const float* rho2_b = (const float*)d_in[18];
    float* out = (float*)d_out;

    const int smem3 = 256 + 3 * 4 * TILEB;  // 196864
    const int smem1 = 256 + 4 * TILEB;      // 65792
    const int smemd = 4 * TILEB;            // 65536
    cudaFuncSetAttribute(k_mm_z,      cudaFuncAttributeMaxDynamicSharedMemorySize, smem3);
    cudaFuncSetAttribute(k_mm_scores, cudaFuncAttributeMaxDynamicSharedMemorySize, smem3);
    cudaFuncSetAttribute(k_mm_out,    cudaFuncAttributeMaxDynamicSharedMemorySize, smem3);
    cudaFuncSetAttribute(k_ds2,       cudaFuncAttributeMaxDynamicSharedMemorySize, smem1);
    cudaFuncSetAttribute(k_ds1,       cudaFuncAttributeMaxDynamicSharedMemorySize, smemd);

    k_conv_w2<<<dim3(DM, DFF / 1024), 256>>>(W2);
    k_conv_x<<<T_TOK, 256>>>(x);
    k_conv_w1<<<DFF, 256>>>(W1);
    k_conv_wr2<<<DFF, 256>>>(Wr2);
    k_ln<<<T_TOK, 256>>>(x, ln_w, ln_b);
    k_mm_z<<<dim3(DFF / 128, T_TOK / 128), 256, smem3>>>();

    k_gemm_router1<<<dim3(DM / 128, T_TOK / 128), 256>>>(Wr1);
    k_conv_h<<<T_TOK, 256>>>();
    k_mm_scores<<<dim3(DFF / 128, T_TOK / 128), 256, smem3>>>();
    k_conv_rho<<<DR, 16>>>(rho1_w);
    k_topk<<<T_TOK, 256>>>(Wr2);

    k_ds1<<<T_TOK, 256, smemd>>>(phi1_w, phi1_b, pl1w, pl1b,
                                 phi2_w, phi2_b, pl2w, pl2b);
    k_ds2<<<(T_TOK * KSEL) / 128, 256, smem1>>>(rho1_b, rho2_w, rho2_b);

    k_mm_out<<<dim3(DM / 128, T_TOK / 128), 256, smem3>>>(out);
}

// round 17
// speedup vs baseline: 1.2351x; 1.0454x over previous
#include <cuda_runtime.h>
#include <cuda_bf16.h>
#include <cstdint>

#define T_TOK 4096
#define DM    1024
#define DFF   4096
#define KSEL  256
#define DH    64
#define DH2   32
#define DR    128
#define TILEB 16384
#define MARG  4e-4f

typedef unsigned long long ull;

__device__ float g_xn[(size_t)T_TOK * DM];
__device__ float g_h[(size_t)T_TOK * DM];
__device__ float g_scores[(size_t)T_TOK * DFF];
__device__ float g_z[(size_t)T_TOK * DFF];
__device__ float g_asel[(size_t)T_TOK * KSEL];
__device__ int   g_idx[(size_t)T_TOK * KSEL];

__device__ ull g_xt0[(size_t)T_TOK * DM / 4],  g_xt1[(size_t)T_TOK * DM / 4];
__device__ ull g_w1t0[(size_t)DFF * DM / 4],   g_w1t1[(size_t)DFF * DM / 4];
__device__ ull g_ht0[(size_t)T_TOK * DM / 4],  g_ht1[(size_t)T_TOK * DM / 4];
__device__ ull g_wr2t0[(size_t)DFF * DM / 4],  g_wr2t1[(size_t)DFF * DM / 4];
__device__ ull g_at0[(size_t)T_TOK * DFF / 4], g_at1[(size_t)T_TOK * DFF / 4];   // zero-init at load
__device__ ull g_w2t0[(size_t)DM * DFF / 4],   g_w2t1[(size_t)DM * DFF / 4];
__device__ ull g_ct0[(size_t)T_TOK * KSEL * DH / 4], g_ct1[(size_t)T_TOK * KSEL * DH / 4];
__device__ ull g_rt0[TILEB / 8], g_rt1[TILEB / 8];

__device__ __forceinline__ float gelu_f(float x) {
    return 0.5f * x * (1.0f + erff(x * 0.7071067811865475f));
}
__device__ __forceinline__ ull pack2(float lo, float hi) {
    ull r; asm("mov.b64 %0, {%1,%2};" : "=l"(r) : "f"(lo), "f"(hi)); return r;
}
__device__ __forceinline__ void unpack2(ull v, float &lo, float &hi) {
    asm("mov.b64 {%0,%1}, %2;" : "=f"(lo), "=f"(hi) : "l"(v));
}
__device__ __forceinline__ ull ffma2(ull a, ull b, ull c) {
    ull d; asm("fma.rn.f32x2 %0, %1, %2, %3;" : "=l"(d) : "l"(a), "l"(b), "l"(c));
    return d;
}
__device__ __forceinline__ uint32_t s2u(const void* p) {
    uint32_t a;
    asm("{ .reg .u64 t; cvta.to.shared.u64 t, %1; cvt.u32.u64 %0, t; }" : "=r"(a) : "l"(p));
    return a;
}
__device__ __forceinline__ void cp16(uint32_t d, const void* s) {
    asm volatile("cp.async.cg.shared.global [%0], [%1], 16;" :: "r"(d), "l"(s) : "memory");
}
__device__ __forceinline__ void cp_commit() {
    asm volatile("cp.async.commit_group;" ::: "memory");
}
template <int N>
__device__ __forceinline__ void cp_wait() {
    asm volatile("cp.async.wait_group %0;" :: "n"(N) : "memory");
}
__device__ __forceinline__ void ldsm4(uint32_t* r, uint32_t addr) {
    asm volatile("ldmatrix.sync.aligned.m8n8.x4.shared.b16 {%0,%1,%2,%3}, [%4];"
                 : "=r"(r[0]), "=r"(r[1]), "=r"(r[2]), "=r"(r[3]) : "r"(addr));
}
__device__ __forceinline__ void mma16816(float* d, const uint32_t* a, const uint32_t* b) {
    asm volatile(
        "mma.sync.aligned.m16n8k16.row.col.f32.bf16.bf16.f32 "
        "{%0,%1,%2,%3}, {%4,%5,%6,%7}, {%8,%9}, {%0,%1,%2,%3};"
        : "+f"(d[0]), "+f"(d[1]), "+f"(d[2]), "+f"(d[3])
        : "r"(a[0]), "r"(a[1]), "r"(a[2]), "r"(a[3]), "r"(b[0]), "r"(b[1]));
}

// ---------------- layernorm -------------------------------------------------
__global__ void __launch_bounds__(256) k_ln(const float* __restrict__ x,
                                            const float* __restrict__ w,
                                            const float* __restrict__ b) {
    __shared__ float red[8];
    int t = blockIdx.x, tid = threadIdx.x;
    float4 v = ((const float4*)(x + (size_t)t * DM))[tid];
    float s = v.x + v.y + v.z + v.w;
    #pragma unroll
    for (int o = 16; o; o >>= 1) s += __shfl_down_sync(0xffffffffu, s, o);
    if ((tid & 31) == 0) red[tid >> 5] = s;
    __syncthreads();
    float tot = 0.f;
    #pragma unroll
    for (int i = 0; i < 8; i++) tot += red[i];
    float mu = tot * (1.0f / DM);
    __syncthreads();
    float dx = v.x - mu, dy = v.y - mu, dz = v.z - mu, dw = v.w - mu;
    float q = dx * dx + dy * dy + dz * dz + dw * dw;
    #pragma unroll
    for (int o = 16; o; o >>= 1) q += __shfl_down_sync(0xffffffffu, q, o);
    if ((tid & 31) == 0) red[tid >> 5] = q;
    __syncthreads();
    float vt = 0.f;
    #pragma unroll
    for (int i = 0; i < 8; i++) vt += red[i];
    float inv = rsqrtf(vt * (1.0f / DM) + 1e-5f);
    float4 wv = ((const float4*)w)[tid];
    float4 bv = ((const float4*)b)[tid];
    float4 o;
    o.x = dx * inv * wv.x + bv.x;
    o.y = dy * inv * wv.y + bv.y;
    o.z = dz * inv * wv.z + bv.z;
    o.w = dw * inv * wv.w + bv.w;
    ((float4*)(g_xn + (size_t)t * DM))[tid] = o;
}

// ---------------- fp32 FFMA2 GEMM, B-skewed (bit-exact vs R1) ---------------
__device__ __forceinline__ void gemm_core(const float* __restrict__ A,
                                          const float* __restrict__ B,
                                          float* __restrict__ C,
                                          int N, bool do_gelu) {
    const int K = 1024;
    __shared__ float As[8][128];
    __shared__ float Bs[8][160];
    int tid = threadIdx.x;
    int m0 = blockIdx.y * 128, n0 = blockIdx.x * 128;
    int lr = tid >> 1;
    int lc = (tid & 1) * 4;
    const float* Ag = A + (size_t)(m0 + lr) * K + lc;
    const float* Bg = B + (size_t)(n0 + lr) * K + lc;
    int tx = tid & 15, ty = tid >> 4;
    int mo = ty * 8, no = tx * 8;
    int lrs = lr + ((lr >> 3) << 1);
    int nos = no + ((no >> 3) << 1);

    ull acc[32];
    #pragma unroll
    for (int i = 0; i < 32; i++) acc[i] = 0ull;

    float4 a4 = *(const float4*)Ag;
    float4 b4 = *(const float4*)Bg;

    #pragma unroll 1
    for (int kt = 0; kt < K / 8; kt++) {
        As[lc + 0][lr] = a4.x; As[lc + 1][lr] = a4.y;
        As[lc + 2][lr] = a4.z; As[lc + 3][lr] = a4.w;
        Bs[lc + 0][lrs] = b4.x; Bs[lc + 1][lrs] = b4.y;
        Bs[lc + 2][lrs] = b4.z; Bs[lc + 3][lrs] = b4.w;
        __syncthreads();
        if (kt + 1 < K / 8) {
            a4 = *(const float4*)(Ag + (kt + 1) * 8);
            b4 = *(const float4*)(Bg + (kt + 1) * 8);
        }
        #pragma unroll
        for (int k = 0; k < 8; k++) {
            float4 aA = *(const float4*)&As[k][mo];
            float4 aB = *(const float4*)&As[k][mo + 4];
            const ull* bp = (const ull*)&Bs[k][nos];
            ull b0 = bp[0], b1 = bp[1], b2 = bp[2], b3 = bp[3];
            float am[8] = {aA.x, aA.y, aA.z, aA.w, aB.x, aB.y, aB.z, aB.w};
            #pragma unroll
            for (int i = 0; i < 8; i++) {
                ull ap = pack2(am[i], am[i]);
                acc[i * 4 + 0] = ffma2(ap, b0, acc[i * 4 + 0]);
                acc[i * 4 + 1] = ffma2(ap, b1, acc[i * 4 + 1]);
                acc[i * 4 + 2] = ffma2(ap, b2, acc[i * 4 + 2]);
                acc[i * 4 + 3] = ffma2(ap, b3, acc[i * 4 + 3]);
            }
        }
        __syncthreads();
    }
    #pragma unroll
    for (int i = 0; i < 8; i++) {
        float* crow = C + (size_t)(m0 + mo + i) * N + n0 + no;
        #pragma unroll
        for (int p = 0; p < 4; p++) {
            float lo, hi;
            unpack2(acc[i * 4 + p], lo, hi);
            if (do_gelu) { lo = gelu_f(lo); hi = gelu_f(hi); }
            crow[2 * p]     = lo;
            crow[2 * p + 1] = hi;
        }
    }
}

__global__ void __launch_bounds__(256, 2) k_gemm_router1(const float* __restrict__ Wr1) {
    gemm_core(g_xn, Wr1, g_h, DM, true);
}

// ---------------- fp32 -> 2 bf16 term tiles ---------------------------------
template <int WIDTH>
__device__ __forceinline__ void conv2w(const float* __restrict__ src,
                                       char* __restrict__ d0,
                                       char* __restrict__ d1) {
    int r = blockIdx.x, tid = threadIdx.x;
    int c0 = blockIdx.y * 1024 + tid * 4;
    float4 v = *(const float4*)(src + (size_t)r * WIDTH + c0);
    int kc = c0 >> 6, cl = c0 & 63;
    uint32_t off = (uint32_t)((r & 127) * 128 + cl * 2);
    off ^= (off >> 3) & 0x70;
    size_t base = ((size_t)((r >> 7) * (WIDTH / 64) + kc)) * TILEB + off;
    float f[4] = {v.x, v.y, v.z, v.w};
    unsigned short u0[4], u1[4];
    #pragma unroll
    for (int j = 0; j < 4; j++) {
        __nv_bfloat16 h0 = __float2bfloat16(f[j]);
        float r1 = f[j] - __bfloat162float(h0);
        u0[j] = __bfloat16_as_ushort(h0);
        u1[j] = __bfloat16_as_ushort(__float2bfloat16(r1));
    }
    ull p0 = (ull)u0[0] | ((ull)u0[1] << 16) | ((ull)u0[2] << 32) | ((ull)u0[3] << 48);
    ull p1 = (ull)u1[0] | ((ull)u1[1] << 16) | ((ull)u1[2] << 32) | ((ull)u1[3] << 48);
    *(ull*)(d0 + base) = p0;
    *(ull*)(d1 + base) = p1;
}

__global__ void __launch_bounds__(256) k_conv_x(const float* __restrict__ s)   { conv2w<DM>(s, (char*)g_xt0, (char*)g_xt1); }
__global__ void __launch_bounds__(256) k_conv_w1(const float* __restrict__ s)  { conv2w<DM>(s, (char*)g_w1t0, (char*)g_w1t1); }
__global__ void __launch_bounds__(256) k_conv_h()                              { conv2w<DM>(g_h, (char*)g_ht0, (char*)g_ht1); }
__global__ void __launch_bounds__(256) k_conv_wr2(const float* __restrict__ s) { conv2w<DM>(s, (char*)g_wr2t0, (char*)g_wr2t1); }
__global__ void __launch_bounds__(256) k_conv_w2(const float* __restrict__ s)  { conv2w<DFF>(s, (char*)g_w2t0, (char*)g_w2t1); }
__global__ void __launch_bounds__(256) k_conv_rho(const float* __restrict__ s) { conv2w<DH>(s, (char*)g_rt0, (char*)g_rt1); }

// ---------------- HMMA bf16 2-term GEMM (3 products, 3-stage) ---------------
template <int NCH>
__device__ __forceinline__ void gemm2t(const ull* __restrict__ A0, const ull* __restrict__ A1,
                                       const ull* __restrict__ B0, const ull* __restrict__ B1,
                                       float* __restrict__ C, int ldc) {
    extern __shared__ char smem[];
    uint32_t sb = (s2u(smem) + 127u) & ~127u;
    const uint32_t STAGE = 4u * TILEB;

    int tid = threadIdx.x, lane = tid & 31, wid = tid >> 5;
    int wm = wid & 1, wn = wid >> 1;
    int bx = blockIdx.x, by = blockIdx.y;

    const ull* As[2] = {A0, A1};
    const ull* Bs[2] = {B0, B1};

    uint32_t rowA[4];
    {
        int ra = wm * 64 + (lane & 15);
        #pragma unroll
        for (int mt = 0; mt < 4; mt++) {
            int rr = ra + mt * 16;
            rowA[mt] = (uint32_t)(rr * 128 + ((rr & 7) << 4));
        }
    }
    uint32_t acol = (uint32_t)((lane >> 4) * 16);
    uint32_t rowB[2];
    {
        int rb = wn * 32 + ((lane >> 4) << 3) + (lane & 7);
        #pragma unroll
        for (int n2 = 0; n2 < 2; n2++) {
            int rr = rb + n2 * 16;
            rowB[n2] = (uint32_t)(rr * 128 + ((rr & 7) << 4));
        }
    }
    uint32_t bcol = (uint32_t)(((lane >> 3) & 1) * 16);

    float acc[64];
    #pragma unroll
    for (int i = 0; i < 64; i++) acc[i] = 0.f;

    auto issue = [&](int kc, int s) {
        uint32_t dst = sb + (uint32_t)s * STAGE;
        #pragma unroll
        for (int t = 0; t < 2; t++) {
            const char* src = (const char*)As[t] + ((size_t)by * NCH + kc) * TILEB;
            #pragma unroll
            for (int j = 0; j < 4; j++) {
                uint32_t o = (uint32_t)(tid + j * 256) * 16;
                cp16(dst + (uint32_t)t * TILEB + o, src + o);
            }
        }
        #pragma unroll
        for (int t = 0; t < 2; t++) {
            const char* src = (const char*)Bs[t] + ((size_t)bx * NCH + kc) * TILEB;
            #pragma unroll
            for (int j = 0; j < 4; j++) {
                uint32_t o = (uint32_t)(tid + j * 256) * 16;
                cp16(dst + (uint32_t)(2 + t) * TILEB + o, src + o);
            }
        }
        cp_commit();
    };

    issue(0, 0);
    issue(1, 1);
    issue(2, 2);

    for (int kc = 0; kc < NCH; kc++) {
        int s = kc % 3;
        if (kc >= NCH - 1)      cp_wait<0>();
        else if (kc == NCH - 2) cp_wait<1>();
        else                    cp_wait<2>();
        __syncthreads();
        uint32_t stg = sb + (uint32_t)s * STAGE;
        #pragma unroll
        for (int ks = 0; ks < 4; ks++) {
            uint32_t ka = (uint32_t)(ks * 32) + acol;
            uint32_t kb = (uint32_t)(ks * 32) + bcol;
            uint32_t af[2][4][4], bf[2][2][4];
            #pragma unroll
            for (int tA = 0; tA < 2; tA++) {
                uint32_t Ab = stg + (uint32_t)tA * TILEB;
                #pragma unroll
                for (int mt = 0; mt < 4; mt++)
                    ldsm4(af[tA][mt], (Ab + rowA[mt]) ^ ka);
            }
            #pragma unroll
            for (int tB = 0; tB < 2; tB++) {
                uint32_t Bb = stg + (uint32_t)(2 + tB) * TILEB;
                ldsm4(bf[tB][0], (Bb + rowB[0]) ^ kb);
                ldsm4(bf[tB][1], (Bb + rowB[1]) ^ kb);
            }
            #pragma unroll
            for (int mt = 0; mt < 4; mt++) {
                #pragma unroll
                for (int nt = 0; nt < 4; nt++)
                    mma16816(&acc[(mt * 4 + nt) * 4], af[0][mt],
                             &bf[0][nt >> 1][(nt & 1) * 2]);
            }
            #pragma unroll
            for (int mt = 0; mt < 4; mt++) {
                #pragma unroll
                for (int nt = 0; nt < 4; nt++)
                    mma16816(&acc[(mt * 4 + nt) * 4], af[0][mt],
                             &bf[1][nt >> 1][(nt & 1) * 2]);
            }
            #pragma unroll
            for (int mt = 0; mt < 4; mt++) {
                #pragma unroll
                for (int nt = 0; nt < 4; nt++)
                    mma16816(&acc[(mt * 4 + nt) * 4], af[1][mt],
                             &bf[0][nt >> 1][(nt & 1) * 2]);
            }
        }
        __syncthreads();
        if (kc + 3 < NCH) issue(kc + 3, (kc + 3) % 3);
    }

    int rbase = by * 128 + wm * 64 + (lane >> 2);
    int cbase = bx * 128 + wn * 32 + (lane & 3) * 2;
    #pragma unroll
    for (int mt = 0; mt < 4; mt++) {
        #pragma unroll
        for (int nt = 0; nt < 4; nt++) {
            const float* a4 = &acc[(mt * 4 + nt) * 4];
            int row = rbase + mt * 16;
            int col = cbase + nt * 8;
            *(float2*)(C + (size_t)row * ldc + col)       = make_float2(a4[0], a4[1]);
            *(float2*)(C + (size_t)(row + 8) * ldc + col) = make_float2(a4[2], a4[3]);
        }
    }
}

__global__ void __launch_bounds__(256, 1) k_mm_z() {
    gemm2t<16>(g_xt0, g_xt1, g_w1t0, g_w1t1, g_z, DFF);
}
__global__ void __launch_bounds__(256, 1) k_mm_scores() {
    gemm2t<16>(g_ht0, g_ht1, g_wr2t0, g_wr2t1, g_scores, DFF);
}
__global__ void __launch_bounds__(256, 1) k_mm_out(float* __restrict__ out) {
    gemm2t<64>(g_at0, g_at1, g_w2t0, g_w2t1, out, DM);
}

// ---------------- top-256: linear-bin select, fully parallel tails ----------
__global__ void __launch_bounds__(256) k_topk(const float* __restrict__ Wr2) {
    __shared__ float r_sum[8], r_mx[8], r_mn[8];
    __shared__ int hist[4][256];
    __shared__ int sh_warp[8];
    __shared__ int sel[256];
    __shared__ int cand[256];
    __shared__ float cand_s[256];
    __shared__ int sh_cnt, sh_nc, sh_b;
    __shared__ float sh_base, sh_bw;

    int t = blockIdx.x, tid = threadIdx.x;
    int lane = tid & 31, w = tid >> 5;
    const float4* srow = (const float4*)(g_scores + (size_t)t * DFF);

    float4 v[4];
    float sum = 0.f, mx = -1e30f, mn = 1e30f;
    #pragma unroll
    for (int j = 0; j < 4; j++) {
        v[j] = srow[tid + j * 256];
        sum += (v[j].x + v[j].y) + (v[j].z + v[j].w);
        mx = fmaxf(mx, fmaxf(fmaxf(v[j].x, v[j].y), fmaxf(v[j].z, v[j].w)));
        mn = fminf(mn, fminf(fminf(v[j].x, v[j].y), fminf(v[j].z, v[j].w)));
    }
    #pragma unroll
    for (int o = 16; o; o >>= 1) {
        sum += __shfl_down_sync(0xffffffffu, sum, o);
        mx = fmaxf(mx, __shfl_down_sync(0xffffffffu, mx, o));
        mn = fminf(mn, __shfl_down_sync(0xffffffffu, mn, o));
    }
    if (lane == 0) { r_sum[w] = sum; r_mx[w] = mx; r_mn[w] = mn; }
    __syncthreads();
    float tsum = 0.f, tmx = -1e30f, tmn = 1e30f;
    #pragma unroll
    for (int i = 0; i < 8; i++) {
        tsum += r_sum[i];
        tmx = fmaxf(tmx, r_mx[i]);
        tmn = fminf(tmn, r_mn[i]);
    }
    float base = tsum * (1.0f / 4096.0f);
    int sub = lane & 3;

    for (int attempt = 0; attempt < 2; attempt++) {
        #pragma unroll
        for (int s = 0; s < 4; s++) hist[s][tid] = 0;
        __syncthreads();
        float inv_bw = 256.0f / (tmx - base);
        #pragma unroll
        for (int j = 0; j < 4; j++) {
            float s4[4] = {v[j].x, v[j].y, v[j].z, v[j].w};
            #pragma unroll
            for (int q = 0; q < 4; q++) {
                float s = s4[q];
                if (s > base) {
                    int b = (int)((s - base) * inv_bw);
                    atomicAdd(&hist[sub][b < 255 ? b : 255], 1);
                }
            }
        }
        __syncthreads();
        int hb = hist[0][255 - tid] + hist[1][255 - tid]
               + hist[2][255 - tid] + hist[3][255 - tid];
        int val = hb;
        #pragma unroll
        for (int o = 1; o < 32; o <<= 1) {
            int n = __shfl_up_sync(0xffffffffu, val, o);
            if (lane >= o) val += n;
        }
        if (lane == 31) sh_warp[w] = val;
        __syncthreads();
        int off = 0, tot = 0;
        #pragma unroll
        for (int ww = 0; ww < 8; ww++) {
            int sw = sh_warp[ww];
            if (ww < w) off += sw;
            tot += sw;
        }
        val += off;
        if (tot >= KSEL) {
            int excl = val - hb;
            if (val >= KSEL && excl < KSEL) {
                sh_b = 255 - tid;
                sh_base = base;
                sh_bw = (tmx - base) * (1.0f / 256.0f);
            }
            __syncthreads();
            break;
        }
        base = tmn;
        __syncthreads();
    }

    float binlo = sh_base + sh_b * sh_bw;
    float binhi = binlo + sh_bw;
    float hif = binhi + MARG, lof = binlo - MARG;

    if (tid == 0) { sh_cnt = 0; sh_nc = 0; }
    __syncthreads();
    #pragma unroll
    for (int j = 0; j < 4; j++) {
        float s4[4] = {v[j].x, v[j].y, v[j].z, v[j].w};
        #pragma unroll
        for (int q = 0; q < 4; q++) {
            float s = s4[q];
            int i = (tid + j * 256) * 4 + q;
            if (s > hif) {
                int p = atomicAdd(&sh_cnt, 1);
                if (p < 256) sel[p] = i;
            } else if (s > lof) {
                int p = atomicAdd(&sh_nc, 1);
                if (p < 256) cand[p] = i;
            }
        }
    }
    __syncthreads();
    int n_in = sh_cnt;
    int ncand = min(sh_nc, 256);
    int need = KSEL - n_in;

    const float4* hr = (const float4*)(g_h + (size_t)t * DM);
    for (int c = w; c < ncand; c += 8) {
        const float4* wr = (const float4*)(Wr2 + (size_t)cand[c] * DM);
        float acc = 0.f;
        #pragma unroll 4
        for (int k = lane; k < DM / 4; k += 32) {
            float4 w4 = wr[k];
            float4 h4 = hr[k];
            acc = fmaf(h4.x, w4.x, acc);
            acc = fmaf(h4.y, w4.y, acc);
            acc = fmaf(h4.z, w4.z, acc);
            acc = fmaf(h4.w, w4.w, acc);
        }
        #pragma unroll
        for (int o = 16; o; o >>= 1) acc += __shfl_down_sync(0xffffffffu, acc, o);
        if (lane == 0) cand_s[c] = acc;
    }
    __syncthreads();

    if (w == 0) {
        for (int c = lane; c < ncand; c += 32) {
            float sc = cand_s[c];
            int ic = cand[c];
            int rank = 0;
            for (int j = 0; j < ncand; j++) {
                float sj = cand_s[j];
                rank += (sj > sc || (sj == sc && cand[j] < ic)) ? 1 : 0;
            }
            if (rank < need) sel[n_in + rank] = ic;
        }
    }
    __syncthreads();

    int i = sel[tid];
    g_idx[(size_t)t * KSEL + tid] = i;
    float z = g_z[(size_t)t * DFF + i];
    g_asel[(size_t)t * KSEL + tid] = gelu_f(z);
}

// ---------------- DS stage 1 ------------------------------------------------
__global__ void __launch_bounds__(256) k_ds1(
    const float* __restrict__ phi1_w, const float* __restrict__ phi1_b,
    const float* __restrict__ ln1w,   const float* __restrict__ ln1b,
    const float* __restrict__ phi2_w, const float* __restrict__ phi2_b,
    const float* __restrict__ ln2w,   const float* __restrict__ ln2b) {
    extern __shared__ char dstage[];
    __shared__ __align__(8) float s_p1w[DH2], s_p1b[DH2], s_l1w[DH2], s_l1b[DH2];
    __shared__ __align__(8) float s_p2w[DH * DH2], s_p2b[DH], s_l2w[DH], s_l2b[DH];
    __shared__ float s_wsum[8][DH];
    __shared__ float s_ctx[DH];

    int t = blockIdx.x, tid = threadIdx.x;
    if (tid < DH2) {
        s_p1w[tid] = phi1_w[tid]; s_p1b[tid] = phi1_b[tid];
        s_l1w[tid] = ln1w[tid];   s_l1b[tid] = ln1b[tid];
    }
    if (tid < DH) {
        s_p2b[tid] = phi2_b[tid]; s_l2w[tid] = ln2w[tid]; s_l2b[tid] = ln2b[tid];
    }
    for (int i = tid; i < DH * DH2; i += 256) s_p2w[i] = phi2_w[i];
    __syncthreads();

    float a = g_asel[(size_t)t * KSEL + tid];

    float e1[DH2];
    float mu = 0.f;
    #pragma unroll
    for (int j = 0; j < DH2; j++) { e1[j] = fmaf(a, s_p1w[j], s_p1b[j]); mu += e1[j]; }
    mu *= (1.0f / DH2);
    float var = 0.f;
    #pragma unroll
    for (int j = 0; j < DH2; j++) { float d = e1[j] - mu; var += d * d; }
    float inv = rsqrtf(var * (1.0f / DH2) + 1e-5f);
    #pragma unroll
    for (int j = 0; j < DH2; j++)
        e1[j] = gelu_f((e1[j] - mu) * inv * s_l1w[j] + s_l1b[j]);

    ull e1p[DH2 / 2];
    #pragma unroll
    for (int j = 0; j < DH2 / 2; j++) e1p[j] = pack2(e1[2 * j], e1[2 * j + 1]);

    float e2[DH];
    #pragma unroll 4
    for (int h = 0; h < DH; h++) {
        const ull* wr = (const ull*)&s_p2w[h * DH2];
        ull a0 = 0ull, a1 = 0ull;
        #pragma unroll
        for (int j = 0; j < DH2 / 2; j += 2) {
            a0 = ffma2(e1p[j + 0], wr[j + 0], a0);
            a1 = ffma2(e1p[j + 1], wr[j + 1], a1);
        }
        float l0, h0, l1, h1;
        unpack2(a0, l0, h0); unpack2(a1, l1, h1);
        e2[h] = ((l0 + h0) + (l1 + h1)) + s_p2b[h];
    }
    float mu2 = 0.f;
    #pragma unroll
    for (int h = 0; h < DH; h++) mu2 += e2[h];
    mu2 *= (1.0f / DH);
    float var2 = 0.f;
    #pragma unroll
    for (int h = 0; h < DH; h++) { float d = e2[h] - mu2; var2 += d * d; }
    float inv2 = rsqrtf(var2 * (1.0f / DH) + 1e-5f);
    #pragma unroll
    for (int h = 0; h < DH; h++)
        e2[h] = (e2[h] - mu2) * inv2 * s_l2w[h] + s_l2b[h];

    int lane = tid & 31, w = tid >> 5;
    #pragma unroll
    for (int h = 0; h < DH; h++) {
        float v = e2[h];
        v += __shfl_down_sync(0xffffffffu, v, 16);
        v += __shfl_down_sync(0xffffffffu, v, 8);
        v += __shfl_down_sync(0xffffffffu, v, 4);
        v += __shfl_down_sync(0xffffffffu, v, 2);
        v += __shfl_down_sync(0xffffffffu, v, 1);
        if (lane == 0) s_wsum[w][h] = v;
    }
    __syncthreads();
    if (tid < DH) {
        float s = 0.f;
        #pragma unroll
        for (int ww = 0; ww < 8; ww++) s += s_wsum[ww][tid];
        s_ctx[tid] = s * (1.0f / KSEL);
    }
    __syncthreads();
    #pragma unroll
    for (int h = 0; h < DH; h++) e2[h] += s_ctx[h];

    int til = tid >> 7;
    uint32_t rbyte = (uint32_t)((tid & 127) * 128);
    #pragma unroll
    for (int j = 0; j < 16; j++) {
        unsigned short u0[4], u1[4];
        #pragma unroll
        for (int q = 0; q < 4; q++) {
            float f = e2[j * 4 + q];
            __nv_bfloat16 h0 = __float2bfloat16(f);
            u0[q] = __bfloat16_as_ushort(h0);
            u1[q] = __bfloat16_as_ushort(__float2bfloat16(f - __bfloat162float(h0)));
        }
        uint32_t off = rbyte + j * 8;
        off ^= (off >> 3) & 0x70;
        *(ull*)(dstage + til * TILEB + off) =
            (ull)u0[0] | ((ull)u0[1] << 16) | ((ull)u0[2] << 32) | ((ull)u0[3] << 48);
        *(ull*)(dstage + 2 * TILEB + til * TILEB + off) =
            (ull)u1[0] | ((ull)u1[1] << 16) | ((ull)u1[2] << 32) | ((ull)u1[3] << 48);
    }
    __syncthreads();
    const float4* ssrc = (const float4*)dstage;
    float4* d0 = (float4*)((char*)g_ct0 + (size_t)(2 * t) * TILEB);
    float4* d1 = (float4*)((char*)g_ct1 + (size_t)(2 * t) * TILEB);
    #pragma unroll
    for (int i = 0; i < 8; i++) d0[tid + i * 256] = ssrc[tid + i * 256];
    #pragma unroll
    for (int i = 0; i < 8; i++) d1[tid + i * 256] = ssrc[2048 + tid + i * 256];
}

// ---------------- DS stage 2 ------------------------------------------------
__global__ void __launch_bounds__(256, 1) k_ds2(const float* __restrict__ rho1_b_,
                                                const float* __restrict__ rho2_w_,
                                                const float* __restrict__ rho2_b_) {
    extern __shared__ char smem[];
    uint32_t sb = (s2u(smem) + 127u) & ~127u;
    __shared__ float s_man[128];
    __shared__ float s_r1b[DR], s_r2w[DR];

    int tid = threadIdx.x, lane = tid & 31, wid = tid >> 5;
    int wm = wid & 1, wn = wid >> 1;
    int bb = blockIdx.x;
    if (tid < DR) { s_r1b[tid] = rho1_b_[tid]; s_r2w[tid] = rho2_w_[tid]; }
    if (tid < 128) s_man[tid] = 0.f;
    float r2b = rho2_b_[0];

    {
        const char* a0 = (const char*)g_ct0 + (size_t)bb * TILEB;
        const char* a1 = (const char*)g_ct1 + (size_t)bb * TILEB;
        #pragma unroll
        for (int j = 0; j < 4; j++) {
            uint32_t o = (uint32_t)(tid + j * 256) * 16;
            cp16(sb + 0 * TILEB + o, a0 + o);
            cp16(sb + 1 * TILEB + o, a1 + o);
            cp16(sb + 2 * TILEB + o, (const char*)g_rt0 + o);
            cp16(sb + 3 * TILEB + o, (const char*)g_rt1 + o);
        }
        cp_commit();
    }

    uint32_t rowA[4];
    {
        int ra = wm * 64 + (lane & 15);
        #pragma unroll
        for (int mt = 0; mt < 4; mt++) {
            int rr = ra + mt * 16;
            rowA[mt] = (uint32_t)(rr * 128 + ((rr & 7) << 4));
        }
    }
    uint32_t acol = (uint32_t)((lane >> 4) * 16);
    uint32_t rowB[2];
    {
        int rb = wn * 32 + ((lane >> 4) << 3) + (lane & 7);
        #pragma unroll
        for (int n2 = 0; n2 < 2; n2++) {
            int rr = rb + n2 * 16;
            rowB[n2] = (uint32_t)(rr * 128 + ((rr & 7) << 4));
        }
    }
    uint32_t bcol = (uint32_t)(((lane >> 3) & 1) * 16);

    float acc[64];
    #pragma unroll
    for (int i = 0; i < 64; i++) acc[i] = 0.f;

    cp_wait<0>();
    __syncthreads();

    #pragma unroll
    for (int ks = 0; ks < 4; ks++) {
        uint32_t ka = (uint32_t)(ks * 32) + acol;
        uint32_t kb = (uint32_t)(ks * 32) + bcol;
        uint32_t af[2][4][4], bf[2][2][4];
        #pragma unroll
        for (int tA = 0; tA < 2; tA++) {
            uint32_t Ab = sb + (uint32_t)tA * TILEB;
            #pragma unroll
            for (int mt = 0; mt < 4; mt++)
                ldsm4(af[tA][mt], (Ab + rowA[mt]) ^ ka);
        }
        #pragma unroll
        for (int tB = 0; tB < 2; tB++) {
            uint32_t Bb = sb + (uint32_t)(2 + tB) * TILEB;
            ldsm4(bf[tB][0], (Bb + rowB[0]) ^ kb);
            ldsm4(bf[tB][1], (Bb + rowB[1]) ^ kb);
        }
        #pragma unroll
        for (int mt = 0; mt < 4; mt++) {
            #pragma unroll
            for (int nt = 0; nt < 4; nt++)
                mma16816(&acc[(mt * 4 + nt) * 4], af[0][mt],
                         &bf[0][nt >> 1][(nt & 1) * 2]);
        }
        #pragma unroll
        for (int mt = 0; mt < 4; mt++) {
            #pragma unroll
            for (int nt = 0; nt < 4; nt++)
                mma16816(&acc[(mt * 4 + nt) * 4], af[0][mt],
                         &bf[1][nt >> 1][(nt & 1) * 2]);
        }
        #pragma unroll
        for (int mt = 0; mt < 4; mt++) {
            #pragma unroll
            for (int nt = 0; nt < 4; nt++)
                mma16816(&acc[(mt * 4 + nt) * 4], af[1][mt],
                         &bf[0][nt >> 1][(nt & 1) * 2]);
        }
    }

    int rloc = wm * 64 + (lane >> 2);
    int cb = wn * 32 + (lane & 3) * 2;
    #pragma unroll
    for (int mt = 0; mt < 4; mt++) {
        #pragma unroll
        for (int hh = 0; hh < 2; hh++) {
            float v = 0.f;
            #pragma unroll
            for (int nt = 0; nt < 4; nt++) {
                int c0 = cb + nt * 8;
                const float* a4 = &acc[(mt * 4 + nt) * 4 + hh * 2];
                v = fmaf(s_r2w[c0],     gelu_f(a4[0] + s_r1b[c0]),     v);
                v = fmaf(s_r2w[c0 + 1], gelu_f(a4[1] + s_r1b[c0 + 1]), v);
            }
            v += __shfl_xor_sync(0xffffffffu, v, 1);
            v += __shfl_xor_sync(0xffffffffu, v, 2);
            if ((lane & 3) == 0)
                atomicAdd(&s_man[rloc + mt * 16 + hh * 8], v);
        }
    }
    __syncthreads();

    if (tid < 128) {
        float man = s_man[tid] + r2b;
        int rg = bb * 128 + tid;
        int t = rg >> 8;
        int i = g_idx[rg];
        __nv_bfloat16 m0 = __float2bfloat16(man);
        __nv_bfloat16 m1 = __float2bfloat16(man - __bfloat162float(m0));
        int kc = i >> 6, cl = i & 63;
        uint32_t off = (uint32_t)((t & 127) * 128 + cl * 2);
        off ^= (off >> 3) & 0x70;
        size_t base = ((size_t)((t >> 7) * (DFF / 64) + kc)) * TILEB + off;
        *(unsigned short*)((char*)g_at0 + base) = __bfloat16_as_ushort(m0);
        *(unsigned short*)((char*)g_at1 + base) = __bfloat16_as_ushort(m1);
    }
}

// ---------------- launch: multi-stream DAG for graph parallelism ------------
extern "C" void kernel_launch(void* const* d_in, const int* in_sizes, int n_in,
                              void* d_out, int out_size) {
    const float* x      = (const float*)d_in[0];
    const float* W1     = (const float*)d_in[1];
    const float* W2     = (const float*)d_in[2];
    const float* Wr1    = (const float*)d_in[3];
    const float* Wr2    = (const float*)d_in[4];
    const float* ln_w   = (const float*)d_in[5];
    const float* ln_b   = (const float*)d_in[6];
    const float* phi1_w = (const float*)d_in[7];
    const float* phi1_b = (const float*)d_in[8];
    const float* pl1w   = (const float*)d_in[9];
    const float* pl1b   = (const float*)d_in[10];
    const float* phi2_w = (const float*)d_in[11];
    const float* phi2_b = (const float*)d_in[12];
    const float* pl2w   = (const float*)d_in[13];
    const float* pl2b   = (const float*)d_in[14];
    const float* rho1_w = (const float*)d_in[15];
    const float* rho1_b = (const float*)d_in[16];
    const float* rho2_w = (const float*)d_in[17];
    const float* rho2_b = (const float*)d_in[18];
    float* out = (float*)d_out;

    const int smem3 = 256 + 3 * 4 * TILEB;  // 196864
    const int smem1 = 256 + 4 * TILEB;      // 65792
    const int smemd = 4 * TILEB;            // 65536

    // One-time resource init (identical work on every call; no device alloc).
    static bool init_done = false;
    static cudaStream_t s1, s2;
    static cudaEvent_t eRoot, eZ, eWr2, eRho, eW2;
    if (!init_done) {
        cudaStreamCreateWithFlags(&s1, cudaStreamNonBlocking);
        cudaStreamCreateWithFlags(&s2, cudaStreamNonBlocking);
        cudaEventCreateWithFlags(&eRoot, cudaEventDisableTiming);
        cudaEventCreateWithFlags(&eZ,    cudaEventDisableTiming);
        cudaEventCreateWithFlags(&eWr2,  cudaEventDisableTiming);
        cudaEventCreateWithFlags(&eRho,  cudaEventDisableTiming);
        cudaEventCreateWithFlags(&eW2,   cudaEventDisableTiming);
        cudaFuncSetAttribute(k_mm_z,      cudaFuncAttributeMaxDynamicSharedMemorySize, smem3);
        cudaFuncSetAttribute(k_mm_scores, cudaFuncAttributeMaxDynamicSharedMemorySize, smem3);
        cudaFuncSetAttribute(k_mm_out,    cudaFuncAttributeMaxDynamicSharedMemorySize, smem3);
        cudaFuncSetAttribute(k_ds2,       cudaFuncAttributeMaxDynamicSharedMemorySize, smem1);
        cudaFuncSetAttribute(k_ds1,       cudaFuncAttributeMaxDynamicSharedMemorySize, smemd);
        init_done = true;
    }

    // fork
    cudaEventRecord(eRoot, 0);
    cudaStreamWaitEvent(s1, eRoot, 0);
    cudaStreamWaitEvent(s2, eRoot, 0);

    // s1: z-chain (independent of router chain until topk)
    k_conv_x<<<T_TOK, 256, 0, s1>>>(x);
    k_conv_w1<<<DFF, 256, 0, s1>>>(W1);
    k_mm_z<<<dim3(DFF / 128, T_TOK / 128), 256, smem3, s1>>>();
    cudaEventRecord(eZ, s1);

    // s2: weight conversions (consumed later on main stream)
    k_conv_wr2<<<DFF, 256, 0, s2>>>(Wr2);
    cudaEventRecord(eWr2, s2);
    k_conv_rho<<<DR, 16, 0, s2>>>(rho1_w);
    cudaEventRecord(eRho, s2);
    k_conv_w2<<<dim3(DM, DFF / 1024), 256, 0, s2>>>(W2);
    cudaEventRecord(eW2, s2);

    // s0 (capture stream): critical path
    k_ln<<<T_TOK, 256>>>(x, ln_w, ln_b);
    k_gemm_router1<<<dim3(DM / 128, T_TOK / 128), 256>>>(Wr1);
    k_conv_h<<<T_TOK, 256>>>();
    cudaStreamWaitEvent(0, eWr2, 0);
    k_mm_scores<<<dim3(DFF / 128, T_TOK / 128), 256, smem3>>>();
    cudaStreamWaitEvent(0, eZ, 0);
    k_topk<<<T_TOK, 256>>>(Wr2);
    k_ds1<<<T_TOK, 256, smemd>>>(phi1_w, phi1_b, pl1w, pl1b,
                                 phi2_w, phi2_b, pl2w, pl2b);
    cudaStreamWaitEvent(0, eRho, 0);
    k_ds2<<<(T_TOK * KSEL) / 128, 256, smem1>>>(rho1_b, rho2_w, rho2_b);
    cudaStreamWaitEvent(0, eW2, 0);
    k_mm_out<<<dim3(DM / 128, T_TOK / 128), 256, smem3>>>(out);
}